// round 1
// baseline (speedup 1.0000x reference)
#include <cuda_runtime.h>
#include <math_constants.h>

// Problem constants
#define BB 2
#define SS 2048
#define DD 1024
#define HH 16
#define DEPTH 64
#define MROWS (BB * SS)          // 4096
#define QKV_N (3 * DD)           // 3072

// Scratch (allocation-free rule: __device__ globals)
__device__ float g_qkv[MROWS * QKV_N];   // [4096, 3072]
__device__ float g_attn[MROWS * DD];     // [4096, 1024]

// ---------------------------------------------------------------------------
// SGEMM with bias: C[M,N] = A[M,K] @ B[K,N] + bias[N]
// BM=BN=128, BK=8, 256 threads, 8x8 per thread. M,N multiples of 128, K of 8.
// ---------------------------------------------------------------------------
__global__ __launch_bounds__(256) void sgemm_bias_kernel(
    const float* __restrict__ A, const float* __restrict__ Bm,
    const float* __restrict__ bias, float* __restrict__ C,
    int N, int K)
{
    constexpr int BM = 128, BN = 128, BK = 8;
    __shared__ float As[BK][BM + 4];   // padded: conflict-free transposed store
    __shared__ float Bs[BK][BN];

    const int tid = threadIdx.x;
    const int tx = tid & 15;           // 0..15 -> col group
    const int ty = tid >> 4;           // 0..15 -> row group
    const int rowBase = blockIdx.y * BM;
    const int colBase = blockIdx.x * BN;

    // A-tile load mapping: one float4 per thread
    const int aRow = tid >> 1;          // 0..127
    const int aCol = (tid & 1) * 4;     // 0 or 4
    // B-tile load mapping: one float4 per thread
    const int bRow = tid >> 5;          // 0..7
    const int bCol = (tid & 31) * 4;    // 0..124

    const float* Aptr = A + (size_t)(rowBase + aRow) * K + aCol;
    const float* Bptr = Bm + (size_t)bRow * N + colBase + bCol;

    float acc[8][8];
    #pragma unroll
    for (int m = 0; m < 8; ++m)
        #pragma unroll
        for (int n = 0; n < 8; ++n) acc[m][n] = 0.f;

    for (int k0 = 0; k0 < K; k0 += BK) {
        float4 av = *(const float4*)(Aptr + k0);
        As[aCol + 0][aRow] = av.x;
        As[aCol + 1][aRow] = av.y;
        As[aCol + 2][aRow] = av.z;
        As[aCol + 3][aRow] = av.w;
        *(float4*)&Bs[bRow][bCol] = *(const float4*)(Bptr + (size_t)k0 * N);
        __syncthreads();

        #pragma unroll
        for (int k = 0; k < BK; ++k) {
            float ar[8], br[8];
            #pragma unroll
            for (int m = 0; m < 8; ++m) ar[m] = As[k][ty * 8 + m];
            #pragma unroll
            for (int n = 0; n < 8; ++n) br[n] = Bs[k][tx * 8 + n];
            #pragma unroll
            for (int m = 0; m < 8; ++m)
                #pragma unroll
                for (int n = 0; n < 8; ++n)
                    acc[m][n] += ar[m] * br[n];
        }
        __syncthreads();
    }

    #pragma unroll
    for (int m = 0; m < 8; ++m) {
        const size_t r = rowBase + ty * 8 + m;
        #pragma unroll
        for (int n = 0; n < 8; n += 4) {
            const int c = colBase + tx * 8 + n;
            float4 v;
            v.x = acc[m][n + 0] + bias[c + 0];
            v.y = acc[m][n + 1] + bias[c + 1];
            v.z = acc[m][n + 2] + bias[c + 2];
            v.w = acc[m][n + 3] + bias[c + 3];
            *(float4*)&C[r * N + c] = v;
        }
    }
}

// ---------------------------------------------------------------------------
// Causal flash attention, fp32. One block = 64 query rows of one (b,h).
// 64 threads: thread t owns query row t. Q/O in registers; K/V tiles + score
// scratch in smem. Skips fully-masked KV tiles (kt > qt).
// qkv layout: [4096, 3072], per row head h occupies [h*192 .. h*192+192):
//   q = +0, k = +64, v = +128  (matches reshape(b,s,H,3*depth)).
// ---------------------------------------------------------------------------
__global__ __launch_bounds__(64) void attn_kernel(
    const float* __restrict__ qkv, float* __restrict__ out)
{
    __shared__ float Ks[64][64];
    __shared__ float Vs[64][64];
    __shared__ float Ps[64][64];   // [j][tid] : per-thread score scratch

    const int tid = threadIdx.x;
    const int qt  = blockIdx.x;        // query tile 0..31
    const int bh  = blockIdx.y;        // 0..31
    const int b   = bh >> 4;
    const int h   = bh & 15;

    const size_t rowQ = (size_t)(b * SS + qt * 64 + tid);
    const float* qptr = qkv + rowQ * QKV_N + h * 192;

    const float scale = 0.125f;        // 1/sqrt(64), folded into q
    float q[DEPTH], o[DEPTH];
    #pragma unroll
    for (int d = 0; d < DEPTH; d += 4) {
        float4 v = *(const float4*)(qptr + d);
        q[d + 0] = v.x * scale; q[d + 1] = v.y * scale;
        q[d + 2] = v.z * scale; q[d + 3] = v.w * scale;
    }
    #pragma unroll
    for (int d = 0; d < DEPTH; ++d) o[d] = 0.f;

    float m = -1e30f, l = 0.f;
    const int kvRowBase = b * SS;

    for (int kt = 0; kt <= qt; ++kt) {
        __syncthreads();  // previous tile fully consumed before overwrite
        // cooperative load of K,V tiles: 64 rows x 16 float4 each
        #pragma unroll
        for (int i = tid; i < 64 * 16; i += 64) {
            const int r = i >> 4;
            const int c = (i & 15) << 2;
            const size_t rr = (size_t)(kvRowBase + kt * 64 + r) * QKV_N + h * 192;
            *(float4*)&Ks[r][c] = *(const float4*)(qkv + rr + 64 + c);
            *(float4*)&Vs[r][c] = *(const float4*)(qkv + rr + 128 + c);
        }
        __syncthreads();

        const bool diag = (kt == qt);
        float tm = -1e30f;
        #pragma unroll 2
        for (int j = 0; j < 64; ++j) {
            float s = 0.f;
            #pragma unroll
            for (int d = 0; d < DEPTH; ++d) s += q[d] * Ks[j][d];
            if (diag && j > tid) s = -1e30f;
            Ps[j][tid] = s;
            tm = fmaxf(tm, s);
        }

        const float mn   = fmaxf(m, tm);
        const float corr = __expf(m - mn);
        l *= corr;
        #pragma unroll
        for (int d = 0; d < DEPTH; ++d) o[d] *= corr;

        #pragma unroll 1
        for (int j = 0; j < 64; ++j) {
            const float p = __expf(Ps[j][tid] - mn);
            l += p;
            #pragma unroll
            for (int d = 0; d < DEPTH; ++d) o[d] += p * Vs[j][d];
        }
        m = mn;
    }

    const float inv = 1.f / l;
    float* optr = out + rowQ * DD + h * DEPTH;
    #pragma unroll
    for (int d = 0; d < DEPTH; d += 4) {
        float4 v;
        v.x = o[d + 0] * inv; v.y = o[d + 1] * inv;
        v.z = o[d + 2] * inv; v.w = o[d + 3] * inv;
        *(float4*)(optr + d) = v;
    }
}

// ---------------------------------------------------------------------------
// Launch: QKV GEMM -> attention -> output GEMM. Graph-capturable (3 launches).
// Inputs (metadata order): x, mask(int32, ignored: causal by construction),
// W_qkv, b_qkv, W_out, b_out. Output fp32 [4096, 1024].
// ---------------------------------------------------------------------------
extern "C" void kernel_launch(void* const* d_in, const int* in_sizes, int n_in,
                              void* d_out, int out_size)
{
    const float* x     = (const float*)d_in[0];
    const float* Wqkv  = (const float*)d_in[2];
    const float* bqkv  = (const float*)d_in[3];
    const float* Wout  = (const float*)d_in[4];
    const float* bout  = (const float*)d_in[5];
    float* out = (float*)d_out;

    void* p_qkv = nullptr;
    void* p_attn = nullptr;
    cudaGetSymbolAddress(&p_qkv, g_qkv);
    cudaGetSymbolAddress(&p_attn, g_attn);
    float* qkv  = (float*)p_qkv;
    float* attn = (float*)p_attn;

    // 1) QKV projection: [4096,1024] @ [1024,3072] + b_qkv
    {
        dim3 grid(QKV_N / 128, MROWS / 128);
        sgemm_bias_kernel<<<grid, 256>>>(x, Wqkv, bqkv, qkv, QKV_N, DD);
    }
    // 2) causal attention: qkv -> attn [4096,1024]
    {
        dim3 grid(SS / 64, BB * HH);
        attn_kernel<<<grid, 64>>>(qkv, attn);
    }
    // 3) output projection: [4096,1024] @ [1024,1024] + b_out
    {
        dim3 grid(DD / 128, MROWS / 128);
        sgemm_bias_kernel<<<grid, 256>>>(attn, Wout, bout, out, DD, DD);
    }
}

// round 3
// speedup vs baseline: 1.3146x; 1.3146x over previous
#include <cuda_runtime.h>
#include <cuda_bf16.h>
#include <cstdint>

// Problem constants
#define BB 2
#define SS 2048
#define DD 1024
#define HH 16
#define DEPTH 64
#define MROWS (BB * SS)          // 4096
#define QKV_N (3 * DD)           // 3072

// Scratch (allocation-free rule: __device__ globals)
__device__ float g_qkv[MROWS * QKV_N];   // [4096, 3072]
__device__ float g_attn[MROWS * DD];     // [4096, 1024]

// ===========================================================================
// Warp-level tensor-core helpers (base-target PTX: sm_80+, works on sm_103)
// ===========================================================================
__device__ __forceinline__ uint32_t smem_u32(const void* p) {
    uint32_t a;
    asm("{ .reg .u64 t; cvta.to.shared.u64 t, %1; cvt.u32.u64 %0, t; }"
        : "=r"(a) : "l"(p));
    return a;
}

__device__ __forceinline__ void ldsm_x4(uint32_t* r, uint32_t a) {
    asm volatile("ldmatrix.sync.aligned.m8n8.x4.shared.b16 {%0,%1,%2,%3}, [%4];"
                 : "=r"(r[0]), "=r"(r[1]), "=r"(r[2]), "=r"(r[3]) : "r"(a));
}

__device__ __forceinline__ void ldsm_x4_t(uint32_t* r, uint32_t a) {
    asm volatile("ldmatrix.sync.aligned.m8n8.x4.trans.shared.b16 {%0,%1,%2,%3}, [%4];"
                 : "=r"(r[0]), "=r"(r[1]), "=r"(r[2]), "=r"(r[3]) : "r"(a));
}

__device__ __forceinline__ void mma16816(float* c, const uint32_t* a,
                                         uint32_t b0, uint32_t b1) {
    asm volatile(
        "mma.sync.aligned.m16n8k16.row.col.f32.bf16.bf16.f32 "
        "{%0,%1,%2,%3}, {%4,%5,%6,%7}, {%8,%9}, {%0,%1,%2,%3};"
        : "+f"(c[0]), "+f"(c[1]), "+f"(c[2]), "+f"(c[3])
        : "r"(a[0]), "r"(a[1]), "r"(a[2]), "r"(a[3]), "r"(b0), "r"(b1));
}

// Split fp32 -> (hi: truncated bf16, lo: rn bf16 of residual). Packs 2 at once.
__device__ __forceinline__ void split2(float x0, float x1,
                                       uint32_t& hi, uint32_t& lo) {
    uint32_t u0 = __float_as_uint(x0), u1 = __float_as_uint(x1);
    uint32_t h0 = u0 & 0xFFFF0000u,    h1 = u1 & 0xFFFF0000u;
    float l0 = x0 - __uint_as_float(h0);
    float l1 = x1 - __uint_as_float(h1);
    hi = (h0 >> 16) | h1;
    __nv_bfloat162 lp = __float22bfloat162_rn(make_float2(l0, l1));
    lo = *reinterpret_cast<uint32_t*>(&lp);
}

// ===========================================================================
// Tensor-core GEMM + bias: C[M,N] = A[M,K] @ B[K,N] + bias[N], fp32 I/O.
// bf16 hi/lo split (3 mma terms). BM=BN=128, BK=32. 256 threads = 8 warps
// in a 4(row) x 2(col) grid; warp tile 32x64 = 2 m-tiles x 8 n-tiles of
// m16n8k16. A in smem as [m][k] (stride 40 bf16), B transposed-on-store to
// ldmatrix.trans-friendly [k][n] (stride 136 bf16). M,N mult of 128, K of 32.
// ===========================================================================
// smem layout (bytes): A_hi 0..10240, A_lo 10240..20480,
//                      B_hi 20480..29184, B_lo 29184..37888
#define A_STRIDE 80      // bytes per A row (32 bf16 + 8 pad)
#define B_STRIDE 272     // bytes per B row (128 bf16 + 8 pad)
#define SM_A_LO 10240
#define SM_B_HI 20480
#define SM_B_LO 29184
#define SM_TOTAL 37888

__global__ __launch_bounds__(256, 1) void tgemm_bias_kernel(
    const float* __restrict__ A, const float* __restrict__ B,
    const float* __restrict__ bias, float* __restrict__ C,
    int N, int K)
{
    __shared__ __align__(16) char sm[SM_TOTAL];
    const uint32_t sb = smem_u32(sm);

    const int tid  = threadIdx.x;
    const int lane = tid & 31;
    const int wid  = tid >> 5;
    const int wm   = wid & 3;          // warp row 0..3 -> rows wm*32
    const int wn   = wid >> 2;         // warp col 0..1 -> cols wn*64

    const int rowBase = blockIdx.y * 128;
    const int colBase = blockIdx.x * 128;

    // ---- global load mappings -------------------------------------------
    const int aRow  = tid >> 1;            // 0..127
    const int aKseg = (tid & 1) * 16;      // 0 or 16
    const int bK    = tid >> 3;            // 0..31
    const int bNseg = (tid & 7) * 16;      // 0..112
    const float* gA = A + (size_t)(rowBase + aRow) * K + aKseg;
    const float* gB = B + colBase + bNseg;
    const uint32_t aStore = sb + (uint32_t)aRow * A_STRIDE + aKseg * 2;
    const uint32_t bStore = sb + SM_B_HI + (uint32_t)bK * B_STRIDE + bNseg * 2;

    // ---- ldmatrix address bases ------------------------------------------
    const int laneM = lane & 15;
    const int laneH = lane >> 4;
    uint32_t aAddr[2], bAddr[4];
    #pragma unroll
    for (int i = 0; i < 2; ++i)
        aAddr[i] = sb + (uint32_t)(wm * 32 + i * 16 + laneM) * A_STRIDE + laneH * 16;
    #pragma unroll
    for (int j = 0; j < 4; ++j)
        bAddr[j] = sb + SM_B_HI + (uint32_t)laneM * B_STRIDE
                 + (uint32_t)(wn * 64 + j * 16 + laneH * 8) * 2;

    float acc[2][8][4];
    #pragma unroll
    for (int i = 0; i < 2; ++i)
        #pragma unroll
        for (int n = 0; n < 8; ++n)
            #pragma unroll
            for (int c = 0; c < 4; ++c) acc[i][n][c] = 0.f;

    const int nChunks = K >> 5;
    for (int ck = 0; ck < nChunks; ++ck) {
        const int k0 = ck << 5;
        __syncthreads();   // previous chunk's ldmatrix done before overwrite

        // ---- A chunk: thread = (row, 16-wide k segment) -------------------
        {
            uint32_t hi[8], lo[8];
            #pragma unroll
            for (int j = 0; j < 4; ++j) {
                float4 v = *(const float4*)(gA + k0 + j * 4);
                split2(v.x, v.y, hi[j * 2], lo[j * 2]);
                split2(v.z, v.w, hi[j * 2 + 1], lo[j * 2 + 1]);
            }
            *(uint4*)(sm + (aStore - sb))            = *(uint4*)(hi);
            *(uint4*)(sm + (aStore - sb) + 16)       = *(uint4*)(hi + 4);
            *(uint4*)(sm + (aStore - sb) + SM_A_LO)      = *(uint4*)(lo);
            *(uint4*)(sm + (aStore - sb) + SM_A_LO + 16) = *(uint4*)(lo + 4);
        }
        // ---- B chunk: thread = (k row, 16-wide n segment), coalesced ------
        {
            uint32_t hi[8], lo[8];
            const float* p = gB + (size_t)(k0 + bK) * N;
            #pragma unroll
            for (int j = 0; j < 4; ++j) {
                float4 v = *(const float4*)(p + j * 4);
                split2(v.x, v.y, hi[j * 2], lo[j * 2]);
                split2(v.z, v.w, hi[j * 2 + 1], lo[j * 2 + 1]);
            }
            *(uint4*)(sm + (bStore - sb))       = *(uint4*)(hi);
            *(uint4*)(sm + (bStore - sb) + 16)  = *(uint4*)(hi + 4);
            *(uint4*)(sm + (bStore - sb) + (SM_B_LO - SM_B_HI))      = *(uint4*)(lo);
            *(uint4*)(sm + (bStore - sb) + (SM_B_LO - SM_B_HI) + 16) = *(uint4*)(lo + 4);
        }
        __syncthreads();

        // ---- 2 k-steps of 16 ----------------------------------------------
        #pragma unroll
        for (int ks = 0; ks < 2; ++ks) {
            const uint32_t aOff = ks * 32;           // 16 bf16 = 32 bytes
            const uint32_t bOff = ks * 16 * B_STRIDE;

            uint32_t ah[2][4], al[2][4], bh[4][4], bl[4][4];
            #pragma unroll
            for (int i = 0; i < 2; ++i) {
                ldsm_x4(ah[i], aAddr[i] + aOff);
                ldsm_x4(al[i], aAddr[i] + aOff + SM_A_LO);
            }
            #pragma unroll
            for (int j = 0; j < 4; ++j) {
                ldsm_x4_t(bh[j], bAddr[j] + bOff);
                ldsm_x4_t(bl[j], bAddr[j] + bOff + (SM_B_LO - SM_B_HI));
            }
            #pragma unroll
            for (int i = 0; i < 2; ++i) {
                #pragma unroll
                for (int n = 0; n < 8; ++n) {
                    const int j = n >> 1, h = (n & 1) * 2;
                    mma16816(acc[i][n], ah[i], bh[j][h], bh[j][h + 1]);
                    mma16816(acc[i][n], ah[i], bl[j][h], bl[j][h + 1]);
                    mma16816(acc[i][n], al[i], bh[j][h], bh[j][h + 1]);
                }
            }
        }
    }

    // ---- epilogue: regs + bias -> gmem ------------------------------------
    #pragma unroll
    for (int i = 0; i < 2; ++i) {
        const int r0 = rowBase + wm * 32 + i * 16 + (lane >> 2);
        #pragma unroll
        for (int n = 0; n < 8; ++n) {
            const int c = colBase + wn * 64 + n * 8 + (lane & 3) * 2;
            const float b0 = bias[c], b1 = bias[c + 1];
            float2 v0 = make_float2(acc[i][n][0] + b0, acc[i][n][1] + b1);
            float2 v1 = make_float2(acc[i][n][2] + b0, acc[i][n][3] + b1);
            *(float2*)&C[(size_t)r0 * N + c]       = v0;
            *(float2*)&C[(size_t)(r0 + 8) * N + c] = v1;
        }
    }
}

// ---------------------------------------------------------------------------
// Causal flash attention, fp32 (unchanged from R1 passing version).
// ---------------------------------------------------------------------------
__global__ __launch_bounds__(64) void attn_kernel(
    const float* __restrict__ qkv, float* __restrict__ out)
{
    __shared__ float Ks[64][64];
    __shared__ float Vs[64][64];
    __shared__ float Ps[64][64];

    const int tid = threadIdx.x;
    const int qt  = blockIdx.x;
    const int bh  = blockIdx.y;
    const int b   = bh >> 4;
    const int h   = bh & 15;

    const size_t rowQ = (size_t)(b * SS + qt * 64 + tid);
    const float* qptr = qkv + rowQ * QKV_N + h * 192;

    const float scale = 0.125f;
    float q[DEPTH], o[DEPTH];
    #pragma unroll
    for (int d = 0; d < DEPTH; d += 4) {
        float4 v = *(const float4*)(qptr + d);
        q[d + 0] = v.x * scale; q[d + 1] = v.y * scale;
        q[d + 2] = v.z * scale; q[d + 3] = v.w * scale;
    }
    #pragma unroll
    for (int d = 0; d < DEPTH; ++d) o[d] = 0.f;

    float m = -1e30f, l = 0.f;
    const int kvRowBase = b * SS;

    for (int kt = 0; kt <= qt; ++kt) {
        __syncthreads();
        #pragma unroll
        for (int i = tid; i < 64 * 16; i += 64) {
            const int r = i >> 4;
            const int c = (i & 15) << 2;
            const size_t rr = (size_t)(kvRowBase + kt * 64 + r) * QKV_N + h * 192;
            *(float4*)&Ks[r][c] = *(const float4*)(qkv + rr + 64 + c);
            *(float4*)&Vs[r][c] = *(const float4*)(qkv + rr + 128 + c);
        }
        __syncthreads();

        const bool diag = (kt == qt);
        float tm = -1e30f;
        #pragma unroll 2
        for (int j = 0; j < 64; ++j) {
            float s = 0.f;
            #pragma unroll
            for (int d = 0; d < DEPTH; ++d) s += q[d] * Ks[j][d];
            if (diag && j > tid) s = -1e30f;
            Ps[j][tid] = s;
            tm = fmaxf(tm, s);
        }

        const float mn   = fmaxf(m, tm);
        const float corr = __expf(m - mn);
        l *= corr;
        #pragma unroll
        for (int d = 0; d < DEPTH; ++d) o[d] *= corr;

        #pragma unroll 1
        for (int j = 0; j < 64; ++j) {
            const float p = __expf(Ps[j][tid] - mn);
            l += p;
            #pragma unroll
            for (int d = 0; d < DEPTH; ++d) o[d] += p * Vs[j][d];
        }
        m = mn;
    }

    const float inv = 1.f / l;
    float* optr = out + rowQ * DD + h * DEPTH;
    #pragma unroll
    for (int d = 0; d < DEPTH; d += 4) {
        float4 v;
        v.x = o[d + 0] * inv; v.y = o[d + 1] * inv;
        v.z = o[d + 2] * inv; v.w = o[d + 3] * inv;
        *(float4*)(optr + d) = v;
    }
}

// ---------------------------------------------------------------------------
// Launch: mma.sync QKV GEMM -> fp32 attention -> mma.sync output GEMM.
// ---------------------------------------------------------------------------
extern "C" void kernel_launch(void* const* d_in, const int* in_sizes, int n_in,
                              void* d_out, int out_size)
{
    const float* x     = (const float*)d_in[0];
    const float* Wqkv  = (const float*)d_in[2];
    const float* bqkv  = (const float*)d_in[3];
    const float* Wout  = (const float*)d_in[4];
    const float* bout  = (const float*)d_in[5];
    float* out = (float*)d_out;

    void* p_qkv = nullptr;
    void* p_attn = nullptr;
    cudaGetSymbolAddress(&p_qkv, g_qkv);
    cudaGetSymbolAddress(&p_attn, g_attn);
    float* qkv  = (float*)p_qkv;
    float* attn = (float*)p_attn;

    // 1) QKV projection: [4096,1024] @ [1024,3072] + b_qkv
    {
        dim3 grid(QKV_N / 128, MROWS / 128);
        tgemm_bias_kernel<<<grid, 256>>>(x, Wqkv, bqkv, qkv, QKV_N, DD);
    }
    // 2) causal attention
    {
        dim3 grid(SS / 64, BB * HH);
        attn_kernel<<<grid, 64>>>(qkv, attn);
    }
    // 3) output projection: [4096,1024] @ [1024,1024] + b_out
    {
        dim3 grid(DD / 128, MROWS / 128);
        tgemm_bias_kernel<<<grid, 256>>>(attn, Wout, bout, out, DD, DD);
    }
}

// round 4
// speedup vs baseline: 2.7056x; 2.0581x over previous
#include <cuda_runtime.h>
#include <cuda_bf16.h>
#include <cstdint>

// Problem constants
#define BB 2
#define SS 2048
#define DD 1024
#define HH 16
#define DEPTH 64
#define MROWS (BB * SS)          // 4096
#define QKV_N (3 * DD)           // 3072

// Scratch (allocation-free rule: __device__ globals)
__device__ float g_qkv[MROWS * QKV_N];   // [4096, 3072]
__device__ float g_attn[MROWS * DD];     // [4096, 1024]

// ===========================================================================
// Warp-level tensor-core helpers (base-target PTX: sm_80+, works on sm_103)
// ===========================================================================
__device__ __forceinline__ uint32_t smem_u32(const void* p) {
    uint32_t a;
    asm("{ .reg .u64 t; cvta.to.shared.u64 t, %1; cvt.u32.u64 %0, t; }"
        : "=r"(a) : "l"(p));
    return a;
}

__device__ __forceinline__ void ldsm_x4(uint32_t* r, uint32_t a) {
    asm volatile("ldmatrix.sync.aligned.m8n8.x4.shared.b16 {%0,%1,%2,%3}, [%4];"
                 : "=r"(r[0]), "=r"(r[1]), "=r"(r[2]), "=r"(r[3]) : "r"(a));
}

__device__ __forceinline__ void ldsm_x4_t(uint32_t* r, uint32_t a) {
    asm volatile("ldmatrix.sync.aligned.m8n8.x4.trans.shared.b16 {%0,%1,%2,%3}, [%4];"
                 : "=r"(r[0]), "=r"(r[1]), "=r"(r[2]), "=r"(r[3]) : "r"(a));
}

__device__ __forceinline__ void mma16816(float* c, const uint32_t* a,
                                         uint32_t b0, uint32_t b1) {
    asm volatile(
        "mma.sync.aligned.m16n8k16.row.col.f32.bf16.bf16.f32 "
        "{%0,%1,%2,%3}, {%4,%5,%6,%7}, {%8,%9}, {%0,%1,%2,%3};"
        : "+f"(c[0]), "+f"(c[1]), "+f"(c[2]), "+f"(c[3])
        : "r"(a[0]), "r"(a[1]), "r"(a[2]), "r"(a[3]), "r"(b0), "r"(b1));
}

// Split fp32 -> (hi: truncated bf16, lo: rn bf16 of residual). Packs 2 at once.
__device__ __forceinline__ void split2(float x0, float x1,
                                       uint32_t& hi, uint32_t& lo) {
    uint32_t u0 = __float_as_uint(x0), u1 = __float_as_uint(x1);
    uint32_t h0 = u0 & 0xFFFF0000u,    h1 = u1 & 0xFFFF0000u;
    float l0 = x0 - __uint_as_float(h0);
    float l1 = x1 - __uint_as_float(h1);
    hi = (h0 >> 16) | h1;
    __nv_bfloat162 lp = __float22bfloat162_rn(make_float2(l0, l1));
    lo = *reinterpret_cast<uint32_t*>(&lp);
}

// ===========================================================================
// Tensor-core GEMM + bias (unchanged from R3, verified): C = A@B + bias
// ===========================================================================
#define A_STRIDE 80
#define B_STRIDE 272
#define SM_A_LO 10240
#define SM_B_HI 20480
#define SM_B_LO 29184
#define SM_TOTAL 37888

__global__ __launch_bounds__(256, 1) void tgemm_bias_kernel(
    const float* __restrict__ A, const float* __restrict__ B,
    const float* __restrict__ bias, float* __restrict__ C,
    int N, int K)
{
    __shared__ __align__(16) char sm[SM_TOTAL];
    const uint32_t sb = smem_u32(sm);

    const int tid  = threadIdx.x;
    const int lane = tid & 31;
    const int wid  = tid >> 5;
    const int wm   = wid & 3;
    const int wn   = wid >> 2;

    const int rowBase = blockIdx.y * 128;
    const int colBase = blockIdx.x * 128;

    const int aRow  = tid >> 1;
    const int aKseg = (tid & 1) * 16;
    const int bK    = tid >> 3;
    const int bNseg = (tid & 7) * 16;
    const float* gA = A + (size_t)(rowBase + aRow) * K + aKseg;
    const float* gB = B + colBase + bNseg;
    const uint32_t aStoreOff = (uint32_t)aRow * A_STRIDE + aKseg * 2;
    const uint32_t bStoreOff = SM_B_HI + (uint32_t)bK * B_STRIDE + bNseg * 2;

    const int laneM = lane & 15;
    const int laneH = lane >> 4;
    uint32_t aAddr[2], bAddr[4];
    #pragma unroll
    for (int i = 0; i < 2; ++i)
        aAddr[i] = sb + (uint32_t)(wm * 32 + i * 16 + laneM) * A_STRIDE + laneH * 16;
    #pragma unroll
    for (int j = 0; j < 4; ++j)
        bAddr[j] = sb + SM_B_HI + (uint32_t)laneM * B_STRIDE
                 + (uint32_t)(wn * 64 + j * 16 + laneH * 8) * 2;

    float acc[2][8][4];
    #pragma unroll
    for (int i = 0; i < 2; ++i)
        #pragma unroll
        for (int n = 0; n < 8; ++n)
            #pragma unroll
            for (int c = 0; c < 4; ++c) acc[i][n][c] = 0.f;

    const int nChunks = K >> 5;
    for (int ck = 0; ck < nChunks; ++ck) {
        const int k0 = ck << 5;
        __syncthreads();

        {
            uint32_t hi[8], lo[8];
            #pragma unroll
            for (int j = 0; j < 4; ++j) {
                float4 v = *(const float4*)(gA + k0 + j * 4);
                split2(v.x, v.y, hi[j * 2], lo[j * 2]);
                split2(v.z, v.w, hi[j * 2 + 1], lo[j * 2 + 1]);
            }
            *(uint4*)(sm + aStoreOff)            = *(uint4*)(hi);
            *(uint4*)(sm + aStoreOff + 16)       = *(uint4*)(hi + 4);
            *(uint4*)(sm + aStoreOff + SM_A_LO)      = *(uint4*)(lo);
            *(uint4*)(sm + aStoreOff + SM_A_LO + 16) = *(uint4*)(lo + 4);
        }
        {
            uint32_t hi[8], lo[8];
            const float* p = gB + (size_t)(k0 + bK) * N;
            #pragma unroll
            for (int j = 0; j < 4; ++j) {
                float4 v = *(const float4*)(p + j * 4);
                split2(v.x, v.y, hi[j * 2], lo[j * 2]);
                split2(v.z, v.w, hi[j * 2 + 1], lo[j * 2 + 1]);
            }
            *(uint4*)(sm + bStoreOff)       = *(uint4*)(hi);
            *(uint4*)(sm + bStoreOff + 16)  = *(uint4*)(hi + 4);
            *(uint4*)(sm + bStoreOff + (SM_B_LO - SM_B_HI))      = *(uint4*)(lo);
            *(uint4*)(sm + bStoreOff + (SM_B_LO - SM_B_HI) + 16) = *(uint4*)(lo + 4);
        }
        __syncthreads();

        #pragma unroll
        for (int ks = 0; ks < 2; ++ks) {
            const uint32_t aOff = ks * 32;
            const uint32_t bOff = ks * 16 * B_STRIDE;

            uint32_t ah[2][4], al[2][4], bh[4][4], bl[4][4];
            #pragma unroll
            for (int i = 0; i < 2; ++i) {
                ldsm_x4(ah[i], aAddr[i] + aOff);
                ldsm_x4(al[i], aAddr[i] + aOff + SM_A_LO);
            }
            #pragma unroll
            for (int j = 0; j < 4; ++j) {
                ldsm_x4_t(bh[j], bAddr[j] + bOff);
                ldsm_x4_t(bl[j], bAddr[j] + bOff + (SM_B_LO - SM_B_HI));
            }
            #pragma unroll
            for (int i = 0; i < 2; ++i) {
                #pragma unroll
                for (int n = 0; n < 8; ++n) {
                    const int j = n >> 1, h = (n & 1) * 2;
                    mma16816(acc[i][n], ah[i], bh[j][h], bh[j][h + 1]);
                    mma16816(acc[i][n], ah[i], bl[j][h], bl[j][h + 1]);
                    mma16816(acc[i][n], al[i], bh[j][h], bh[j][h + 1]);
                }
            }
        }
    }

    #pragma unroll
    for (int i = 0; i < 2; ++i) {
        const int r0 = rowBase + wm * 32 + i * 16 + (lane >> 2);
        #pragma unroll
        for (int n = 0; n < 8; ++n) {
            const int c = colBase + wn * 64 + n * 8 + (lane & 3) * 2;
            const float b0 = bias[c], b1 = bias[c + 1];
            float2 v0 = make_float2(acc[i][n][0] + b0, acc[i][n][1] + b1);
            float2 v1 = make_float2(acc[i][n][2] + b0, acc[i][n][3] + b1);
            *(float2*)&C[(size_t)r0 * N + c]       = v0;
            *(float2*)&C[(size_t)(r0 + 8) * N + c] = v1;
        }
    }
}

// ===========================================================================
// Tensor-core causal flash attention (FA2 layout), bf16 hi/lo split.
// CTA = 128 q rows of one (b,h); 8 warps x 16 rows. KV tiles of 64.
// QK^T: 3-term split (Qh*Kh + Qh*Kl + Ql*Kh); PV: Ph*Vh + Ph*Vl + Pl*Vh.
// smem stride 144B per 64-bf16 row (odd*16B -> conflict-free ldmatrix).
// ===========================================================================
#define ASTR 144
#define FQ_HI 0
#define FQ_LO 18432
#define FK_HI 36864
#define FK_LO 46080
#define FV_HI 55296
#define FV_LO 64512
#define FATTN_SMEM 73728

__global__ __launch_bounds__(256, 1) void fattn_kernel(
    const float* __restrict__ qkv, float* __restrict__ out)
{
    extern __shared__ char sm[];
    const uint32_t sb = smem_u32(sm);

    const int tid  = threadIdx.x;
    const int lane = tid & 31;
    const int w    = tid >> 5;          // warp 0..7 -> q rows w*16..+16
    const int g    = lane >> 2;         // row in tile (and +8)
    const int t2   = (lane & 3) * 2;    // col pair

    const int qt = (gridDim.x - 1) - blockIdx.x;   // heavy tiles first
    const int bh = blockIdx.y;
    const int b  = bh >> 4;
    const int h  = bh & 15;
    const int qbase = qt * 128;

    // ---- stage Q (scaled by 1/8, hi/lo split) ------------------------------
    {
        const int qrow = tid >> 1;
        const int qc0  = (tid & 1) * 32;
        const float* qp = qkv + (size_t)(b * SS + qbase + qrow) * QKV_N + h * 192 + qc0;
        char* dh = sm + FQ_HI + qrow * ASTR + qc0 * 2;
        char* dl = sm + FQ_LO + qrow * ASTR + qc0 * 2;
        #pragma unroll
        for (int j = 0; j < 32; j += 4) {
            float4 v = *(const float4*)(qp + j);
            uint32_t h0, l0, h1, l1;
            split2(v.x * 0.125f, v.y * 0.125f, h0, l0);
            split2(v.z * 0.125f, v.w * 0.125f, h1, l1);
            *(uint2*)(dh + j * 2) = make_uint2(h0, h1);
            *(uint2*)(dl + j * 2) = make_uint2(l0, l1);
        }
    }
    __syncthreads();

    // ---- Q fragments, kept in registers for the whole kv loop --------------
    uint32_t qh[4][4], ql[4][4];
    {
        const uint32_t qa = sb + (uint32_t)(w * 16 + (lane & 15)) * ASTR + (lane >> 4) * 16;
        #pragma unroll
        for (int ks = 0; ks < 4; ++ks) {
            ldsm_x4(qh[ks], qa + FQ_HI + ks * 32);
            ldsm_x4(ql[ks], qa + FQ_LO + ks * 32);
        }
    }

    float O[8][4];
    #pragma unroll
    for (int n = 0; n < 8; ++n)
        #pragma unroll
        for (int c = 0; c < 4; ++c) O[n][c] = 0.f;
    float m0 = -1e30f, m1 = -1e30f, l0 = 0.f, l1 = 0.f;

    // fragment address bases
    const uint32_t kAddrB = sb + FK_HI
        + (uint32_t)((lane & 7) + ((lane >> 4) & 1) * 8) * ASTR + ((lane >> 3) & 1) * 16;
    const uint32_t vAddrB = sb + FV_HI
        + (uint32_t)(lane & 15) * ASTR + (uint32_t)(lane >> 4) * 16;

    const int rowbase = qbase + w * 16;
    const int ktMax = qbase / 64 + 1;   // inclusive

    for (int kt = 0; kt <= ktMax; ++kt) {
        const int kvbase = kt * 64;
        __syncthreads();   // all warps done with previous K/V tiles
        // ---- stage K,V tiles (hi/lo split) ---------------------------------
        {
            const int r  = tid >> 2;
            const int c0 = (tid & 3) * 16;
            const float* kp = qkv + (size_t)(b * SS + kvbase + r) * QKV_N + h * 192 + 64 + c0;
            char* kh = sm + FK_HI + r * ASTR + c0 * 2;
            char* kl = sm + FK_LO + r * ASTR + c0 * 2;
            char* vh = sm + FV_HI + r * ASTR + c0 * 2;
            char* vl = sm + FV_LO + r * ASTR + c0 * 2;
            #pragma unroll
            for (int j = 0; j < 16; j += 4) {
                float4 v = *(const float4*)(kp + j);
                uint32_t a0, b0, a1, b1;
                split2(v.x, v.y, a0, b0);
                split2(v.z, v.w, a1, b1);
                *(uint2*)(kh + j * 2) = make_uint2(a0, a1);
                *(uint2*)(kl + j * 2) = make_uint2(b0, b1);
                float4 u = *(const float4*)(kp + 64 + j);
                split2(u.x, u.y, a0, b0);
                split2(u.z, u.w, a1, b1);
                *(uint2*)(vh + j * 2) = make_uint2(a0, a1);
                *(uint2*)(vl + j * 2) = make_uint2(b0, b1);
            }
        }
        __syncthreads();

        if (kvbase > rowbase + 15) continue;   // warp tile fully masked

        // ---- S = Q K^T ------------------------------------------------------
        float S[8][4];
        #pragma unroll
        for (int n = 0; n < 8; ++n)
            #pragma unroll
            for (int c = 0; c < 4; ++c) S[n][c] = 0.f;

        #pragma unroll
        for (int ks = 0; ks < 4; ++ks) {
            uint32_t kb[4][4], kl_[4][4];
            #pragma unroll
            for (int j = 0; j < 4; ++j) {
                ldsm_x4(kb[j],  kAddrB + (uint32_t)j * 16 * ASTR + ks * 32);
                ldsm_x4(kl_[j], kAddrB + (FK_LO - FK_HI) + (uint32_t)j * 16 * ASTR + ks * 32);
            }
            #pragma unroll
            for (int n = 0; n < 8; ++n) {
                const int j = n >> 1, hh = (n & 1) * 2;
                mma16816(S[n], qh[ks], kb[j][hh],  kb[j][hh + 1]);
                mma16816(S[n], qh[ks], kl_[j][hh], kl_[j][hh + 1]);
                mma16816(S[n], ql[ks], kb[j][hh],  kb[j][hh + 1]);
            }
        }

        // ---- causal mask (diagonal tiles only) ------------------------------
        if (kvbase + 63 > rowbase) {
            #pragma unroll
            for (int n = 0; n < 8; ++n) {
                const int colb = kvbase + n * 8 + t2;
                if (colb > rowbase + g)          S[n][0] = -1e30f;
                if (colb + 1 > rowbase + g)      S[n][1] = -1e30f;
                if (colb > rowbase + g + 8)      S[n][2] = -1e30f;
                if (colb + 1 > rowbase + g + 8)  S[n][3] = -1e30f;
            }
        }

        // ---- online softmax --------------------------------------------------
        float tm0 = -1e30f, tm1 = -1e30f;
        #pragma unroll
        for (int n = 0; n < 8; ++n) {
            tm0 = fmaxf(tm0, fmaxf(S[n][0], S[n][1]));
            tm1 = fmaxf(tm1, fmaxf(S[n][2], S[n][3]));
        }
        tm0 = fmaxf(tm0, __shfl_xor_sync(0xFFFFFFFFu, tm0, 1));
        tm0 = fmaxf(tm0, __shfl_xor_sync(0xFFFFFFFFu, tm0, 2));
        tm1 = fmaxf(tm1, __shfl_xor_sync(0xFFFFFFFFu, tm1, 1));
        tm1 = fmaxf(tm1, __shfl_xor_sync(0xFFFFFFFFu, tm1, 2));

        const float mn0 = fmaxf(m0, tm0);
        const float mn1 = fmaxf(m1, tm1);
        const float cr0 = __expf(m0 - mn0);
        const float cr1 = __expf(m1 - mn1);
        l0 *= cr0; l1 *= cr1;
        #pragma unroll
        for (int n = 0; n < 8; ++n) {
            O[n][0] *= cr0; O[n][1] *= cr0;
            O[n][2] *= cr1; O[n][3] *= cr1;
        }
        #pragma unroll
        for (int n = 0; n < 8; ++n) {
            S[n][0] = __expf(S[n][0] - mn0);
            S[n][1] = __expf(S[n][1] - mn0);
            S[n][2] = __expf(S[n][2] - mn1);
            S[n][3] = __expf(S[n][3] - mn1);
            l0 += S[n][0] + S[n][1];
            l1 += S[n][2] + S[n][3];
        }
        m0 = mn0; m1 = mn1;

        // ---- pack P fragments (hi/lo) ----------------------------------------
        uint32_t ph[4][4], pl[4][4];
        #pragma unroll
        for (int j = 0; j < 4; ++j) {
            split2(S[2 * j][0],     S[2 * j][1],     ph[j][0], pl[j][0]);
            split2(S[2 * j][2],     S[2 * j][3],     ph[j][1], pl[j][1]);
            split2(S[2 * j + 1][0], S[2 * j + 1][1], ph[j][2], pl[j][2]);
            split2(S[2 * j + 1][2], S[2 * j + 1][3], ph[j][3], pl[j][3]);
        }

        // ---- O += P V ---------------------------------------------------------
        #pragma unroll
        for (int ks = 0; ks < 4; ++ks) {
            uint32_t vb[4][4], vl_[4][4];
            #pragma unroll
            for (int j = 0; j < 4; ++j) {
                const uint32_t va = vAddrB + (uint32_t)ks * 16 * ASTR + (uint32_t)j * 32;
                ldsm_x4_t(vb[j],  va);
                ldsm_x4_t(vl_[j], va + (FV_LO - FV_HI));
            }
            #pragma unroll
            for (int n = 0; n < 8; ++n) {
                const int j = n >> 1, hh = (n & 1) * 2;
                mma16816(O[n], ph[ks], vb[j][hh],  vb[j][hh + 1]);
                mma16816(O[n], ph[ks], vl_[j][hh], vl_[j][hh + 1]);
                mma16816(O[n], pl[ks], vb[j][hh],  vb[j][hh + 1]);
            }
        }
    }

    // ---- finalize: reduce l across quad, scale, store -----------------------
    l0 += __shfl_xor_sync(0xFFFFFFFFu, l0, 1);
    l0 += __shfl_xor_sync(0xFFFFFFFFu, l0, 2);
    l1 += __shfl_xor_sync(0xFFFFFFFFu, l1, 1);
    l1 += __shfl_xor_sync(0xFFFFFFFFu, l1, 2);
    const float inv0 = 1.f / l0;
    const float inv1 = 1.f / l1;

    const size_t row0 = (size_t)(b * SS + rowbase + g);
    #pragma unroll
    for (int n = 0; n < 8; ++n) {
        const int c = h * DEPTH + n * 8 + t2;
        *(float2*)&out[row0 * DD + c] =
            make_float2(O[n][0] * inv0, O[n][1] * inv0);
        *(float2*)&out[(row0 + 8) * DD + c] =
            make_float2(O[n][2] * inv1, O[n][3] * inv1);
    }
}

// ---------------------------------------------------------------------------
// Launch: mma.sync QKV GEMM -> mma.sync flash attention -> mma.sync out GEMM.
// ---------------------------------------------------------------------------
extern "C" void kernel_launch(void* const* d_in, const int* in_sizes, int n_in,
                              void* d_out, int out_size)
{
    const float* x     = (const float*)d_in[0];
    const float* Wqkv  = (const float*)d_in[2];
    const float* bqkv  = (const float*)d_in[3];
    const float* Wout  = (const float*)d_in[4];
    const float* bout  = (const float*)d_in[5];
    float* out = (float*)d_out;

    void* p_qkv = nullptr;
    void* p_attn = nullptr;
    cudaGetSymbolAddress(&p_qkv, g_qkv);
    cudaGetSymbolAddress(&p_attn, g_attn);
    float* qkv  = (float*)p_qkv;
    float* attn = (float*)p_attn;

    cudaFuncSetAttribute(fattn_kernel,
                         cudaFuncAttributeMaxDynamicSharedMemorySize,
                         FATTN_SMEM);

    // 1) QKV projection: [4096,1024] @ [1024,3072] + b_qkv
    {
        dim3 grid(QKV_N / 128, MROWS / 128);
        tgemm_bias_kernel<<<grid, 256>>>(x, Wqkv, bqkv, qkv, QKV_N, DD);
    }
    // 2) causal flash attention (tensor cores)
    {
        dim3 grid(SS / 128, BB * HH);
        fattn_kernel<<<grid, 256, FATTN_SMEM>>>(qkv, attn);
    }
    // 3) output projection: [4096,1024] @ [1024,1024] + b_out
    {
        dim3 grid(DD / 128, MROWS / 128);
        tgemm_bias_kernel<<<grid, 256>>>(attn, Wout, bout, out, DD, DD);
    }
}

// round 6
// speedup vs baseline: 3.1609x; 1.1683x over previous
#include <cuda_runtime.h>
#include <cuda_bf16.h>
#include <cstdint>

// Problem constants
#define BB 2
#define SS 2048
#define DD 1024
#define HH 16
#define DEPTH 64
#define MROWS (BB * SS)          // 4096
#define QKV_N (3 * DD)           // 3072

// Scratch (allocation-free rule: __device__ globals), all bf16 hi/lo pairs
__device__ __nv_bfloat16 g_xh[MROWS * DD],    g_xl[MROWS * DD];
__device__ __nv_bfloat16 g_wqh[DD * QKV_N],   g_wql[DD * QKV_N];
__device__ __nv_bfloat16 g_woh[DD * DD],      g_wol[DD * DD];
__device__ __nv_bfloat16 g_qh[MROWS * QKV_N], g_ql[MROWS * QKV_N];
__device__ __nv_bfloat16 g_ah[MROWS * DD],    g_al[MROWS * DD];

// ===========================================================================
// Helpers (base-target PTX: sm_80+, works on sm_103)
// ===========================================================================
__device__ __forceinline__ uint32_t smem_u32(const void* p) {
    uint32_t a;
    asm("{ .reg .u64 t; cvta.to.shared.u64 t, %1; cvt.u32.u64 %0, t; }"
        : "=r"(a) : "l"(p));
    return a;
}

__device__ __forceinline__ void ldsm_x4(uint32_t* r, uint32_t a) {
    asm volatile("ldmatrix.sync.aligned.m8n8.x4.shared.b16 {%0,%1,%2,%3}, [%4];"
                 : "=r"(r[0]), "=r"(r[1]), "=r"(r[2]), "=r"(r[3]) : "r"(a));
}

__device__ __forceinline__ void ldsm_x4_t(uint32_t* r, uint32_t a) {
    asm volatile("ldmatrix.sync.aligned.m8n8.x4.trans.shared.b16 {%0,%1,%2,%3}, [%4];"
                 : "=r"(r[0]), "=r"(r[1]), "=r"(r[2]), "=r"(r[3]) : "r"(a));
}

__device__ __forceinline__ void mma16816(float* c, const uint32_t* a,
                                         uint32_t b0, uint32_t b1) {
    asm volatile(
        "mma.sync.aligned.m16n8k16.row.col.f32.bf16.bf16.f32 "
        "{%0,%1,%2,%3}, {%4,%5,%6,%7}, {%8,%9}, {%0,%1,%2,%3};"
        : "+f"(c[0]), "+f"(c[1]), "+f"(c[2]), "+f"(c[3])
        : "r"(a[0]), "r"(a[1]), "r"(a[2]), "r"(a[3]), "r"(b0), "r"(b1));
}

__device__ __forceinline__ void cpa16(uint32_t d, const void* s) {
    asm volatile("cp.async.cg.shared.global [%0], [%1], 16;" :: "r"(d), "l"(s));
}
#define CP_COMMIT() asm volatile("cp.async.commit_group;" ::: "memory")
#define CP_WAIT1()  asm volatile("cp.async.wait_group 1;" ::: "memory")

// Split fp32 -> (hi: truncated bf16, lo: rn bf16 of residual). Packs 2 at once.
__device__ __forceinline__ void split2(float x0, float x1,
                                       uint32_t& hi, uint32_t& lo) {
    uint32_t u0 = __float_as_uint(x0), u1 = __float_as_uint(x1);
    uint32_t h0 = u0 & 0xFFFF0000u,    h1 = u1 & 0xFFFF0000u;
    float l0 = x0 - __uint_as_float(h0);
    float l1 = x1 - __uint_as_float(h1);
    hi = (h0 >> 16) | h1;
    __nv_bfloat162 lp = __float22bfloat162_rn(make_float2(l0, l1));
    lo = *reinterpret_cast<uint32_t*>(&lp);
}

// ===========================================================================
// Prep: elementwise fp32 -> bf16 hi/lo split
// ===========================================================================
__global__ void split_kernel(const float* __restrict__ in,
                             __nv_bfloat16* __restrict__ oh,
                             __nv_bfloat16* __restrict__ ol, int n)
{
    const int i = (blockIdx.x * blockDim.x + threadIdx.x) * 4;
    if (i >= n) return;
    float4 v = *(const float4*)(in + i);
    uint32_t h0, l0, h1, l1;
    split2(v.x, v.y, h0, l0);
    split2(v.z, v.w, h1, l1);
    *(uint2*)(oh + i) = make_uint2(h0, h1);
    *(uint2*)(ol + i) = make_uint2(l0, l1);
}

// ===========================================================================
// bf16 hi/lo GEMM + bias, cp.async double-buffered. BM=BN=128, BK=32.
// 8 warps (4x2), warp tile 32x64. 3-term split MMA. fp32 or split-bf16 out.
// Stage layout (37888 B): Ah 0(128x80) Al 10240 Bh 20480(32x272) Bl 29184
// ===========================================================================
#define GSTAGE 37888
#define G_SMEM (2 * GSTAGE)

template<bool SPLIT_OUT>
__global__ __launch_bounds__(256, 2) void tgemm_bf16_kernel(
    const __nv_bfloat16* __restrict__ Ah, const __nv_bfloat16* __restrict__ Al,
    const __nv_bfloat16* __restrict__ Bh, const __nv_bfloat16* __restrict__ Bl,
    const float* __restrict__ bias,
    void* __restrict__ Cp, void* __restrict__ Clp,
    int N, int K)
{
    extern __shared__ char sm[];
    const uint32_t sb = smem_u32(sm);

    const int tid  = threadIdx.x;
    const int lane = tid & 31;
    const int wid  = tid >> 5;
    const int wm   = wid & 3;
    const int wn   = wid >> 2;

    const int rowBase = blockIdx.y * 128;
    const int colBase = blockIdx.x * 128;

    // loader mappings
    const int aRow = tid >> 1;
    const int aE0  = (tid & 1) * 16;     // element offset in chunk
    const int bK   = tid >> 3;
    const int bE0  = (tid & 7) * 16;

    // ldmatrix bases (relative to stage start)
    const int laneM = lane & 15;
    const int laneH = lane >> 4;
    uint32_t aRel[2], bRel[4];
    #pragma unroll
    for (int i = 0; i < 2; ++i)
        aRel[i] = (uint32_t)(wm * 32 + i * 16 + laneM) * 80 + laneH * 16;
    #pragma unroll
    for (int j = 0; j < 4; ++j)
        bRel[j] = 20480u + (uint32_t)laneM * 272
                + (uint32_t)(wn * 64 + j * 16 + laneH * 8) * 2;

    float acc[2][8][4];
    #pragma unroll
    for (int i = 0; i < 2; ++i)
        #pragma unroll
        for (int n = 0; n < 8; ++n)
            #pragma unroll
            for (int c = 0; c < 4; ++c) acc[i][n][c] = 0.f;

    const int nChunks = K >> 5;

    auto issue = [&](int ck) {
        const uint32_t st = sb + (uint32_t)(ck & 1) * GSTAGE;
        const int k0 = ck << 5;
        {   // A rows
            const size_t gi = (size_t)(rowBase + aRow) * K + k0 + aE0;
            const uint32_t d = st + (uint32_t)aRow * 80 + aE0 * 2;
            cpa16(d,              Ah + gi);
            cpa16(d + 16,         Ah + gi + 8);
            cpa16(d + 10240,      Al + gi);
            cpa16(d + 10240 + 16, Al + gi + 8);
        }
        {   // B rows [k][n]
            const size_t gi = (size_t)(k0 + bK) * N + colBase + bE0;
            const uint32_t d = st + 20480u + (uint32_t)bK * 272 + bE0 * 2;
            cpa16(d,             Bh + gi);
            cpa16(d + 16,        Bh + gi + 8);
            cpa16(d + 8704,      Bl + gi);
            cpa16(d + 8704 + 16, Bl + gi + 8);
        }
    };

    issue(0); CP_COMMIT();
    issue(1); CP_COMMIT();

    for (int ck = 0; ck < nChunks; ++ck) {
        CP_WAIT1();
        __syncthreads();
        const uint32_t st = sb + (uint32_t)(ck & 1) * GSTAGE;

        #pragma unroll
        for (int ks = 0; ks < 2; ++ks) {
            const uint32_t aOff = st + ks * 32;
            const uint32_t bOff = st + ks * 16 * 272;
            uint32_t ah[2][4], al[2][4], bh[4][4], bl[4][4];
            #pragma unroll
            for (int i = 0; i < 2; ++i) {
                ldsm_x4(ah[i], aRel[i] + aOff);
                ldsm_x4(al[i], aRel[i] + aOff + 10240);
            }
            #pragma unroll
            for (int j = 0; j < 4; ++j) {
                ldsm_x4_t(bh[j], bRel[j] + bOff);
                ldsm_x4_t(bl[j], bRel[j] + bOff + 8704);
            }
            #pragma unroll
            for (int i = 0; i < 2; ++i) {
                #pragma unroll
                for (int n = 0; n < 8; ++n) {
                    const int j = n >> 1, h = (n & 1) * 2;
                    mma16816(acc[i][n], ah[i], bh[j][h], bh[j][h + 1]);
                    mma16816(acc[i][n], ah[i], bl[j][h], bl[j][h + 1]);
                    mma16816(acc[i][n], al[i], bh[j][h], bh[j][h + 1]);
                }
            }
        }
        __syncthreads();
        if (ck + 2 < nChunks) issue(ck + 2);
        CP_COMMIT();
    }

    // ---- epilogue ----------------------------------------------------------
    #pragma unroll
    for (int i = 0; i < 2; ++i) {
        const int r0 = rowBase + wm * 32 + i * 16 + (lane >> 2);
        #pragma unroll
        for (int n = 0; n < 8; ++n) {
            const int c = colBase + wn * 64 + n * 8 + (lane & 3) * 2;
            const float b0 = bias[c], b1 = bias[c + 1];
            const float v00 = acc[i][n][0] + b0, v01 = acc[i][n][1] + b1;
            const float v10 = acc[i][n][2] + b0, v11 = acc[i][n][3] + b1;
            if (SPLIT_OUT) {
                __nv_bfloat16* Ch = (__nv_bfloat16*)Cp;
                __nv_bfloat16* Cl = (__nv_bfloat16*)Clp;
                uint32_t hi, lo;
                split2(v00, v01, hi, lo);
                *(uint32_t*)&Ch[(size_t)r0 * N + c] = hi;
                *(uint32_t*)&Cl[(size_t)r0 * N + c] = lo;
                split2(v10, v11, hi, lo);
                *(uint32_t*)&Ch[(size_t)(r0 + 8) * N + c] = hi;
                *(uint32_t*)&Cl[(size_t)(r0 + 8) * N + c] = lo;
            } else {
                float* C = (float*)Cp;
                *(float2*)&C[(size_t)r0 * N + c]       = make_float2(v00, v01);
                *(float2*)&C[(size_t)(r0 + 8) * N + c] = make_float2(v10, v11);
            }
        }
    }
}

// ===========================================================================
// Tensor-core causal flash attention, bf16 hi/lo inputs + outputs.
// CTA = 128 q rows x one (b,h); 8 warps x 16 rows; kv tiles of 64.
// 1/sqrt(d) applied to fp32 scores (exact power of 2).
// ===========================================================================
#define ASTR 144
#define FQ_HI 0
#define FQ_LO 18432
#define FK_HI 36864
#define FK_LO 46080
#define FV_HI 55296
#define FV_LO 64512
#define FATTN_SMEM 73728

__global__ __launch_bounds__(256, 1) void fattn_kernel(
    const __nv_bfloat16* __restrict__ qkvh,
    const __nv_bfloat16* __restrict__ qkvl,
    __nv_bfloat16* __restrict__ outh,
    __nv_bfloat16* __restrict__ outl)
{
    extern __shared__ char sm[];
    const uint32_t sb = smem_u32(sm);

    const int tid  = threadIdx.x;
    const int lane = tid & 31;
    const int w    = tid >> 5;
    const int g    = lane >> 2;
    const int t2   = (lane & 3) * 2;

    const int qt = (gridDim.x - 1) - blockIdx.x;   // heavy tiles first
    const int bh = blockIdx.y;
    const int b  = bh >> 4;
    const int h  = bh & 15;
    const int qbase = qt * 128;

    // ---- stage Q: 2 threads/row, 32 elems (4 x uint4) each ------------------
    {
        const int qrow = tid >> 1;
        const int qc0  = (tid & 1) * 32;                    // element offset
        const size_t gi = (size_t)(b * SS + qbase + qrow) * QKV_N + h * 192 + qc0;
        char* dh = sm + FQ_HI + qrow * ASTR + qc0 * 2;      // byte offset
        char* dl = sm + FQ_LO + qrow * ASTR + qc0 * 2;
        #pragma unroll
        for (int j = 0; j < 4; ++j) {
            *(uint4*)(dh + j * 16) = *(const uint4*)(qkvh + gi + j * 8);
            *(uint4*)(dl + j * 16) = *(const uint4*)(qkvl + gi + j * 8);
        }
    }
    __syncthreads();

    // ---- Q fragments in registers for whole kv loop ------------------------
    uint32_t qh[4][4], ql[4][4];
    {
        const uint32_t qa = sb + (uint32_t)(w * 16 + (lane & 15)) * ASTR + (lane >> 4) * 16;
        #pragma unroll
        for (int ks = 0; ks < 4; ++ks) {
            ldsm_x4(qh[ks], qa + FQ_HI + ks * 32);
            ldsm_x4(ql[ks], qa + FQ_LO + ks * 32);
        }
    }

    float O[8][4];
    #pragma unroll
    for (int n = 0; n < 8; ++n)
        #pragma unroll
        for (int c = 0; c < 4; ++c) O[n][c] = 0.f;
    float m0 = -1e30f, m1 = -1e30f, l0 = 0.f, l1 = 0.f;

    const uint32_t kAddrB = sb + FK_HI
        + (uint32_t)((lane & 7) + ((lane >> 4) & 1) * 8) * ASTR + ((lane >> 3) & 1) * 16;
    const uint32_t vAddrB = sb + FV_HI
        + (uint32_t)(lane & 15) * ASTR + (uint32_t)(lane >> 4) * 16;

    const int rowbase = qbase + w * 16;
    const int ktMax = qbase / 64 + 1;

    for (int kt = 0; kt <= ktMax; ++kt) {
        const int kvbase = kt * 64;
        __syncthreads();
        // ---- stage K,V: 4 threads/row, 16 elems (2 x uint4) per region ------
        {
            const int r  = tid >> 2;
            const int c0 = (tid & 3) * 16;                  // element offset
            const size_t gi = (size_t)(b * SS + kvbase + r) * QKV_N + h * 192 + 64 + c0;
            char* kh = sm + FK_HI + r * ASTR + c0 * 2;
            char* kl = sm + FK_LO + r * ASTR + c0 * 2;
            char* vh = sm + FV_HI + r * ASTR + c0 * 2;
            char* vl = sm + FV_LO + r * ASTR + c0 * 2;
            #pragma unroll
            for (int j = 0; j < 2; ++j) {
                *(uint4*)(kh + j * 16) = *(const uint4*)(qkvh + gi + j * 8);
                *(uint4*)(kl + j * 16) = *(const uint4*)(qkvl + gi + j * 8);
                *(uint4*)(vh + j * 16) = *(const uint4*)(qkvh + gi + 64 + j * 8);
                *(uint4*)(vl + j * 16) = *(const uint4*)(qkvl + gi + 64 + j * 8);
            }
        }
        __syncthreads();

        if (kvbase > rowbase + 15) continue;

        // ---- S = Q K^T -------------------------------------------------------
        float S[8][4];
        #pragma unroll
        for (int n = 0; n < 8; ++n)
            #pragma unroll
            for (int c = 0; c < 4; ++c) S[n][c] = 0.f;

        #pragma unroll
        for (int ks = 0; ks < 4; ++ks) {
            uint32_t kb[4][4], kl_[4][4];
            #pragma unroll
            for (int j = 0; j < 4; ++j) {
                ldsm_x4(kb[j],  kAddrB + (uint32_t)j * 16 * ASTR + ks * 32);
                ldsm_x4(kl_[j], kAddrB + (FK_LO - FK_HI) + (uint32_t)j * 16 * ASTR + ks * 32);
            }
            #pragma unroll
            for (int n = 0; n < 8; ++n) {
                const int j = n >> 1, hh = (n & 1) * 2;
                mma16816(S[n], qh[ks], kb[j][hh],  kb[j][hh + 1]);
                mma16816(S[n], qh[ks], kl_[j][hh], kl_[j][hh + 1]);
                mma16816(S[n], ql[ks], kb[j][hh],  kb[j][hh + 1]);
            }
        }

        // scale (exact) + causal mask
        #pragma unroll
        for (int n = 0; n < 8; ++n) {
            S[n][0] *= 0.125f; S[n][1] *= 0.125f;
            S[n][2] *= 0.125f; S[n][3] *= 0.125f;
        }
        if (kvbase + 63 > rowbase) {
            #pragma unroll
            for (int n = 0; n < 8; ++n) {
                const int colb = kvbase + n * 8 + t2;
                if (colb > rowbase + g)          S[n][0] = -1e30f;
                if (colb + 1 > rowbase + g)      S[n][1] = -1e30f;
                if (colb > rowbase + g + 8)      S[n][2] = -1e30f;
                if (colb + 1 > rowbase + g + 8)  S[n][3] = -1e30f;
            }
        }

        // ---- online softmax ---------------------------------------------------
        float tm0 = -1e30f, tm1 = -1e30f;
        #pragma unroll
        for (int n = 0; n < 8; ++n) {
            tm0 = fmaxf(tm0, fmaxf(S[n][0], S[n][1]));
            tm1 = fmaxf(tm1, fmaxf(S[n][2], S[n][3]));
        }
        tm0 = fmaxf(tm0, __shfl_xor_sync(0xFFFFFFFFu, tm0, 1));
        tm0 = fmaxf(tm0, __shfl_xor_sync(0xFFFFFFFFu, tm0, 2));
        tm1 = fmaxf(tm1, __shfl_xor_sync(0xFFFFFFFFu, tm1, 1));
        tm1 = fmaxf(tm1, __shfl_xor_sync(0xFFFFFFFFu, tm1, 2));

        const float mn0 = fmaxf(m0, tm0);
        const float mn1 = fmaxf(m1, tm1);
        const float cr0 = __expf(m0 - mn0);
        const float cr1 = __expf(m1 - mn1);
        l0 *= cr0; l1 *= cr1;
        #pragma unroll
        for (int n = 0; n < 8; ++n) {
            O[n][0] *= cr0; O[n][1] *= cr0;
            O[n][2] *= cr1; O[n][3] *= cr1;
        }
        #pragma unroll
        for (int n = 0; n < 8; ++n) {
            S[n][0] = __expf(S[n][0] - mn0);
            S[n][1] = __expf(S[n][1] - mn0);
            S[n][2] = __expf(S[n][2] - mn1);
            S[n][3] = __expf(S[n][3] - mn1);
            l0 += S[n][0] + S[n][1];
            l1 += S[n][2] + S[n][3];
        }
        m0 = mn0; m1 = mn1;

        // ---- pack P fragments (hi/lo) -----------------------------------------
        uint32_t ph[4][4], pl[4][4];
        #pragma unroll
        for (int j = 0; j < 4; ++j) {
            split2(S[2 * j][0],     S[2 * j][1],     ph[j][0], pl[j][0]);
            split2(S[2 * j][2],     S[2 * j][3],     ph[j][1], pl[j][1]);
            split2(S[2 * j + 1][0], S[2 * j + 1][1], ph[j][2], pl[j][2]);
            split2(S[2 * j + 1][2], S[2 * j + 1][3], ph[j][3], pl[j][3]);
        }

        // ---- O += P V -----------------------------------------------------------
        #pragma unroll
        for (int ks = 0; ks < 4; ++ks) {
            uint32_t vb[4][4], vl_[4][4];
            #pragma unroll
            for (int j = 0; j < 4; ++j) {
                const uint32_t va = vAddrB + (uint32_t)ks * 16 * ASTR + (uint32_t)j * 32;
                ldsm_x4_t(vb[j],  va);
                ldsm_x4_t(vl_[j], va + (FV_LO - FV_HI));
            }
            #pragma unroll
            for (int n = 0; n < 8; ++n) {
                const int j = n >> 1, hh = (n & 1) * 2;
                mma16816(O[n], ph[ks], vb[j][hh],  vb[j][hh + 1]);
                mma16816(O[n], ph[ks], vl_[j][hh], vl_[j][hh + 1]);
                mma16816(O[n], pl[ks], vb[j][hh],  vb[j][hh + 1]);
            }
        }
    }

    // ---- finalize: reduce l, scale, split-store ------------------------------
    l0 += __shfl_xor_sync(0xFFFFFFFFu, l0, 1);
    l0 += __shfl_xor_sync(0xFFFFFFFFu, l0, 2);
    l1 += __shfl_xor_sync(0xFFFFFFFFu, l1, 1);
    l1 += __shfl_xor_sync(0xFFFFFFFFu, l1, 2);
    const float inv0 = 1.f / l0;
    const float inv1 = 1.f / l1;

    const size_t row0 = (size_t)(b * SS + rowbase + g);
    #pragma unroll
    for (int n = 0; n < 8; ++n) {
        const int c = h * DEPTH + n * 8 + t2;
        uint32_t hi, lo;
        split2(O[n][0] * inv0, O[n][1] * inv0, hi, lo);
        *(uint32_t*)&outh[row0 * DD + c] = hi;
        *(uint32_t*)&outl[row0 * DD + c] = lo;
        split2(O[n][2] * inv1, O[n][3] * inv1, hi, lo);
        *(uint32_t*)&outh[(row0 + 8) * DD + c] = hi;
        *(uint32_t*)&outl[(row0 + 8) * DD + c] = lo;
    }
}

// ---------------------------------------------------------------------------
// Launch: 3 split preps -> QKV GEMM(split out) -> flash attn -> out GEMM(f32).
// ---------------------------------------------------------------------------
extern "C" void kernel_launch(void* const* d_in, const int* in_sizes, int n_in,
                              void* d_out, int out_size)
{
    const float* x     = (const float*)d_in[0];
    const float* Wqkv  = (const float*)d_in[2];
    const float* bqkv  = (const float*)d_in[3];
    const float* Wout  = (const float*)d_in[4];
    const float* bout  = (const float*)d_in[5];
    float* out = (float*)d_out;

    __nv_bfloat16 *xh, *xl, *wqh, *wql, *woh, *wol, *qh, *ql, *ah, *al;
    { void* p; cudaGetSymbolAddress(&p, g_xh);  xh  = (__nv_bfloat16*)p; }
    { void* p; cudaGetSymbolAddress(&p, g_xl);  xl  = (__nv_bfloat16*)p; }
    { void* p; cudaGetSymbolAddress(&p, g_wqh); wqh = (__nv_bfloat16*)p; }
    { void* p; cudaGetSymbolAddress(&p, g_wql); wql = (__nv_bfloat16*)p; }
    { void* p; cudaGetSymbolAddress(&p, g_woh); woh = (__nv_bfloat16*)p; }
    { void* p; cudaGetSymbolAddress(&p, g_wol); wol = (__nv_bfloat16*)p; }
    { void* p; cudaGetSymbolAddress(&p, g_qh);  qh  = (__nv_bfloat16*)p; }
    { void* p; cudaGetSymbolAddress(&p, g_ql);  ql  = (__nv_bfloat16*)p; }
    { void* p; cudaGetSymbolAddress(&p, g_ah);  ah  = (__nv_bfloat16*)p; }
    { void* p; cudaGetSymbolAddress(&p, g_al);  al  = (__nv_bfloat16*)p; }

    static bool attr_set = false;
    if (!attr_set) {
        cudaFuncSetAttribute(tgemm_bf16_kernel<true>,
                             cudaFuncAttributeMaxDynamicSharedMemorySize, G_SMEM);
        cudaFuncSetAttribute(tgemm_bf16_kernel<false>,
                             cudaFuncAttributeMaxDynamicSharedMemorySize, G_SMEM);
        cudaFuncSetAttribute(fattn_kernel,
                             cudaFuncAttributeMaxDynamicSharedMemorySize, FATTN_SMEM);
        attr_set = true;
    }

    // 0) pre-split inputs/weights to bf16 hi/lo
    split_kernel<<<(MROWS * DD / 4 + 255) / 256, 256>>>(x, xh, xl, MROWS * DD);
    split_kernel<<<(DD * QKV_N / 4 + 255) / 256, 256>>>(Wqkv, wqh, wql, DD * QKV_N);
    split_kernel<<<(DD * DD / 4 + 255) / 256, 256>>>(Wout, woh, wol, DD * DD);

    // 1) QKV projection -> split bf16 qkv
    {
        dim3 grid(QKV_N / 128, MROWS / 128);
        tgemm_bf16_kernel<true><<<grid, 256, G_SMEM>>>(
            xh, xl, wqh, wql, bqkv, qh, ql, QKV_N, DD);
    }
    // 2) causal flash attention -> split bf16 attn
    {
        dim3 grid(SS / 128, BB * HH);
        fattn_kernel<<<grid, 256, FATTN_SMEM>>>(qh, ql, ah, al);
    }
    // 3) output projection -> fp32 out
    {
        dim3 grid(DD / 128, MROWS / 128);
        tgemm_bf16_kernel<false><<<grid, 256, G_SMEM>>>(
            ah, al, woh, wol, bout, out, nullptr, DD, DD);
    }
}

// round 7
// speedup vs baseline: 3.2034x; 1.0135x over previous
#include <cuda_runtime.h>
#include <cuda_bf16.h>
#include <cstdint>

// Problem constants
#define BB 2
#define SS 2048
#define DD 1024
#define HH 16
#define DEPTH 64
#define MROWS (BB * SS)          // 4096
#define QKV_N (3 * DD)           // 3072

// Scratch (allocation-free rule: __device__ globals), all bf16 hi/lo pairs
__device__ __nv_bfloat16 g_xh[MROWS * DD],    g_xl[MROWS * DD];
__device__ __nv_bfloat16 g_wqh[DD * QKV_N],   g_wql[DD * QKV_N];
__device__ __nv_bfloat16 g_woh[DD * DD],      g_wol[DD * DD];
__device__ __nv_bfloat16 g_qh[MROWS * QKV_N], g_ql[MROWS * QKV_N];
__device__ __nv_bfloat16 g_ah[MROWS * DD],    g_al[MROWS * DD];

// ===========================================================================
// Helpers (base-target PTX: sm_80+, works on sm_103)
// ===========================================================================
__device__ __forceinline__ uint32_t smem_u32(const void* p) {
    uint32_t a;
    asm("{ .reg .u64 t; cvta.to.shared.u64 t, %1; cvt.u32.u64 %0, t; }"
        : "=r"(a) : "l"(p));
    return a;
}

__device__ __forceinline__ void ldsm_x4(uint32_t* r, uint32_t a) {
    asm volatile("ldmatrix.sync.aligned.m8n8.x4.shared.b16 {%0,%1,%2,%3}, [%4];"
                 : "=r"(r[0]), "=r"(r[1]), "=r"(r[2]), "=r"(r[3]) : "r"(a));
}

__device__ __forceinline__ void ldsm_x4_t(uint32_t* r, uint32_t a) {
    asm volatile("ldmatrix.sync.aligned.m8n8.x4.trans.shared.b16 {%0,%1,%2,%3}, [%4];"
                 : "=r"(r[0]), "=r"(r[1]), "=r"(r[2]), "=r"(r[3]) : "r"(a));
}

__device__ __forceinline__ void mma16816(float* c, const uint32_t* a,
                                         uint32_t b0, uint32_t b1) {
    asm volatile(
        "mma.sync.aligned.m16n8k16.row.col.f32.bf16.bf16.f32 "
        "{%0,%1,%2,%3}, {%4,%5,%6,%7}, {%8,%9}, {%0,%1,%2,%3};"
        : "+f"(c[0]), "+f"(c[1]), "+f"(c[2]), "+f"(c[3])
        : "r"(a[0]), "r"(a[1]), "r"(a[2]), "r"(a[3]), "r"(b0), "r"(b1));
}

__device__ __forceinline__ void cpa16(uint32_t d, const void* s) {
    asm volatile("cp.async.cg.shared.global [%0], [%1], 16;" :: "r"(d), "l"(s));
}
#define CP_COMMIT() asm volatile("cp.async.commit_group;" ::: "memory")
#define CP_WAIT1()  asm volatile("cp.async.wait_group 1;" ::: "memory")
#define CP_WAIT0()  asm volatile("cp.async.wait_group 0;" ::: "memory")

// Split fp32 -> (hi: truncated bf16, lo: rn bf16 of residual). Packs 2 at once.
__device__ __forceinline__ void split2(float x0, float x1,
                                       uint32_t& hi, uint32_t& lo) {
    uint32_t u0 = __float_as_uint(x0), u1 = __float_as_uint(x1);
    uint32_t h0 = u0 & 0xFFFF0000u,    h1 = u1 & 0xFFFF0000u;
    float l0 = x0 - __uint_as_float(h0);
    float l1 = x1 - __uint_as_float(h1);
    hi = (h0 >> 16) | h1;
    __nv_bfloat162 lp = __float22bfloat162_rn(make_float2(l0, l1));
    lo = *reinterpret_cast<uint32_t*>(&lp);
}

// ===========================================================================
// Prep: elementwise fp32 -> bf16 hi/lo split
// ===========================================================================
__global__ void split_kernel(const float* __restrict__ in,
                             __nv_bfloat16* __restrict__ oh,
                             __nv_bfloat16* __restrict__ ol, int n)
{
    const int i = (blockIdx.x * blockDim.x + threadIdx.x) * 4;
    if (i >= n) return;
    float4 v = *(const float4*)(in + i);
    uint32_t h0, l0, h1, l1;
    split2(v.x, v.y, h0, l0);
    split2(v.z, v.w, h1, l1);
    *(uint2*)(oh + i) = make_uint2(h0, h1);
    *(uint2*)(ol + i) = make_uint2(l0, l1);
}

// ===========================================================================
// bf16 hi/lo GEMM + bias, cp.async 3-stage pipeline, ONE sync per chunk.
// BM=BN=128, BK=32, 8 warps (4x2), warp tile 32x64, 3-term split MMA.
// Stage (37888 B): Ah 0(128x80) Al 10240 Bh 20480(32x272) Bl 29184
// ===========================================================================
#define GSTAGE 37888
#define G_SMEM (3 * GSTAGE)

template<bool SPLIT_OUT>
__global__ __launch_bounds__(256, 2) void tgemm_bf16_kernel(
    const __nv_bfloat16* __restrict__ Ah, const __nv_bfloat16* __restrict__ Al,
    const __nv_bfloat16* __restrict__ Bh, const __nv_bfloat16* __restrict__ Bl,
    const float* __restrict__ bias,
    void* __restrict__ Cp, void* __restrict__ Clp,
    int N, int K)
{
    extern __shared__ char sm[];
    const uint32_t sb = smem_u32(sm);

    const int tid  = threadIdx.x;
    const int lane = tid & 31;
    const int wid  = tid >> 5;
    const int wm   = wid & 3;
    const int wn   = wid >> 2;

    const int rowBase = blockIdx.y * 128;
    const int colBase = blockIdx.x * 128;

    // loader mappings
    const int aRow = tid >> 1;
    const int aE0  = (tid & 1) * 16;
    const int bK   = tid >> 3;
    const int bE0  = (tid & 7) * 16;

    // ldmatrix bases (relative to stage start)
    const int laneM = lane & 15;
    const int laneH = lane >> 4;
    uint32_t aRel[2], bRel[4];
    #pragma unroll
    for (int i = 0; i < 2; ++i)
        aRel[i] = (uint32_t)(wm * 32 + i * 16 + laneM) * 80 + laneH * 16;
    #pragma unroll
    for (int j = 0; j < 4; ++j)
        bRel[j] = 20480u + (uint32_t)laneM * 272
                + (uint32_t)(wn * 64 + j * 16 + laneH * 8) * 2;

    float acc[2][8][4];
    #pragma unroll
    for (int i = 0; i < 2; ++i)
        #pragma unroll
        for (int n = 0; n < 8; ++n)
            #pragma unroll
            for (int c = 0; c < 4; ++c) acc[i][n][c] = 0.f;

    const int nChunks = K >> 5;

    auto issue = [&](int ck, uint32_t stOff) {
        const uint32_t st = sb + stOff;
        const int k0 = ck << 5;
        {   // A rows
            const size_t gi = (size_t)(rowBase + aRow) * K + k0 + aE0;
            const uint32_t d = st + (uint32_t)aRow * 80 + aE0 * 2;
            cpa16(d,              Ah + gi);
            cpa16(d + 16,         Ah + gi + 8);
            cpa16(d + 10240,      Al + gi);
            cpa16(d + 10240 + 16, Al + gi + 8);
        }
        {   // B rows [k][n]
            const size_t gi = (size_t)(k0 + bK) * N + colBase + bE0;
            const uint32_t d = st + 20480u + (uint32_t)bK * 272 + bE0 * 2;
            cpa16(d,             Bh + gi);
            cpa16(d + 16,        Bh + gi + 8);
            cpa16(d + 8704,      Bl + gi);
            cpa16(d + 8704 + 16, Bl + gi + 8);
        }
    };

    issue(0, 0); CP_COMMIT();
    issue(1, GSTAGE); CP_COMMIT();

    uint32_t stOff = 0;   // stage of chunk ck
    for (int ck = 0; ck < nChunks; ++ck) {
        CP_WAIT1();          // chunk ck complete (ck+1 may be in flight)
        __syncthreads();     // visibility + everyone done with chunk ck-1
        if (ck + 2 < nChunks) {
            uint32_t issOff = stOff + 2 * GSTAGE;
            if (issOff >= 3 * GSTAGE) issOff -= 3 * GSTAGE;
            issue(ck + 2, issOff);   // stage consumed at ck-1 -> free
        }
        CP_COMMIT();

        const uint32_t st = sb + stOff;
        #pragma unroll
        for (int ks = 0; ks < 2; ++ks) {
            const uint32_t aOff = st + ks * 32;
            const uint32_t bOff = st + ks * 16 * 272;
            uint32_t ah[2][4], al[2][4], bh[4][4], bl[4][4];
            #pragma unroll
            for (int i = 0; i < 2; ++i) {
                ldsm_x4(ah[i], aRel[i] + aOff);
                ldsm_x4(al[i], aRel[i] + aOff + 10240);
            }
            #pragma unroll
            for (int j = 0; j < 4; ++j) {
                ldsm_x4_t(bh[j], bRel[j] + bOff);
                ldsm_x4_t(bl[j], bRel[j] + bOff + 8704);
            }
            #pragma unroll
            for (int i = 0; i < 2; ++i) {
                #pragma unroll
                for (int n = 0; n < 8; ++n) {
                    const int j = n >> 1, h = (n & 1) * 2;
                    mma16816(acc[i][n], ah[i], bh[j][h], bh[j][h + 1]);
                    mma16816(acc[i][n], ah[i], bl[j][h], bl[j][h + 1]);
                    mma16816(acc[i][n], al[i], bh[j][h], bh[j][h + 1]);
                }
            }
        }
        stOff += GSTAGE;
        if (stOff >= 3 * GSTAGE) stOff = 0;
    }
    CP_WAIT0();   // retire tail groups cleanly

    // ---- epilogue ----------------------------------------------------------
    #pragma unroll
    for (int i = 0; i < 2; ++i) {
        const int r0 = rowBase + wm * 32 + i * 16 + (lane >> 2);
        #pragma unroll
        for (int n = 0; n < 8; ++n) {
            const int c = colBase + wn * 64 + n * 8 + (lane & 3) * 2;
            const float b0 = bias[c], b1 = bias[c + 1];
            const float v00 = acc[i][n][0] + b0, v01 = acc[i][n][1] + b1;
            const float v10 = acc[i][n][2] + b0, v11 = acc[i][n][3] + b1;
            if (SPLIT_OUT) {
                __nv_bfloat16* Ch = (__nv_bfloat16*)Cp;
                __nv_bfloat16* Cl = (__nv_bfloat16*)Clp;
                uint32_t hi, lo;
                split2(v00, v01, hi, lo);
                *(uint32_t*)&Ch[(size_t)r0 * N + c] = hi;
                *(uint32_t*)&Cl[(size_t)r0 * N + c] = lo;
                split2(v10, v11, hi, lo);
                *(uint32_t*)&Ch[(size_t)(r0 + 8) * N + c] = hi;
                *(uint32_t*)&Cl[(size_t)(r0 + 8) * N + c] = lo;
            } else {
                float* C = (float*)Cp;
                *(float2*)&C[(size_t)r0 * N + c]       = make_float2(v00, v01);
                *(float2*)&C[(size_t)(r0 + 8) * N + c] = make_float2(v10, v11);
            }
        }
    }
}

// ===========================================================================
// Tensor-core causal flash attention, bf16 hi/lo I/O.
// CTA = 128 q rows x one (b,h); 8 warps x 16 rows; kv tiles of 64.
// K/V staged via cp.async, double-buffered: ONE sync per kv tile.
// smem: Q_hi 0, Q_lo 18432; KV stage s at 36864 + s*36864:
//       K_hi +0, K_lo +9216, V_hi +18432, V_lo +27648. Total 110592.
// ===========================================================================
#define ASTR 144
#define FQ_LO 18432
#define FKV0 36864
#define KVSTG 36864
#define FATTN_SMEM 110592

__global__ __launch_bounds__(256, 2) void fattn_kernel(
    const __nv_bfloat16* __restrict__ qkvh,
    const __nv_bfloat16* __restrict__ qkvl,
    __nv_bfloat16* __restrict__ outh,
    __nv_bfloat16* __restrict__ outl)
{
    extern __shared__ char sm[];
    const uint32_t sb = smem_u32(sm);

    const int tid  = threadIdx.x;
    const int lane = tid & 31;
    const int w    = tid >> 5;
    const int g    = lane >> 2;
    const int t2   = (lane & 3) * 2;

    const int qt = (gridDim.x - 1) - blockIdx.x;   // heavy tiles first
    const int bh = blockIdx.y;
    const int b  = bh >> 4;
    const int h  = bh & 15;
    const int qbase = qt * 128;

    // K/V loader mapping (cp.async): 4 threads/row, 16 elems per region each
    const int kvR  = tid >> 2;
    const int kvC0 = (tid & 3) * 16;
    auto issueKV = [&](int kt) {
        const uint32_t st = sb + FKV0 + (uint32_t)(kt & 1) * KVSTG;
        const size_t gi = (size_t)(b * SS + kt * 64 + kvR) * QKV_N + h * 192 + 64 + kvC0;
        const uint32_t d = st + (uint32_t)kvR * ASTR + kvC0 * 2;
        cpa16(d,              qkvh + gi);          // K hi
        cpa16(d + 16,         qkvh + gi + 8);
        cpa16(d + 9216,       qkvl + gi);          // K lo
        cpa16(d + 9216 + 16,  qkvl + gi + 8);
        cpa16(d + 18432,      qkvh + gi + 64);     // V hi
        cpa16(d + 18432 + 16, qkvh + gi + 72);
        cpa16(d + 27648,      qkvl + gi + 64);     // V lo
        cpa16(d + 27648 + 16, qkvl + gi + 72);
    };

    // ---- stage Q (plain stores) + kick off kv tile 0 -------------------------
    {
        const int qrow = tid >> 1;
        const int qc0  = (tid & 1) * 32;
        const size_t gi = (size_t)(b * SS + qbase + qrow) * QKV_N + h * 192 + qc0;
        char* dh = sm + qrow * ASTR + qc0 * 2;
        char* dl = sm + FQ_LO + qrow * ASTR + qc0 * 2;
        #pragma unroll
        for (int j = 0; j < 4; ++j) {
            *(uint4*)(dh + j * 16) = *(const uint4*)(qkvh + gi + j * 8);
            *(uint4*)(dl + j * 16) = *(const uint4*)(qkvl + gi + j * 8);
        }
    }
    issueKV(0); CP_COMMIT();
    __syncthreads();

    // ---- Q fragments in registers for whole kv loop --------------------------
    uint32_t qh[4][4], ql[4][4];
    {
        const uint32_t qa = sb + (uint32_t)(w * 16 + (lane & 15)) * ASTR + (lane >> 4) * 16;
        #pragma unroll
        for (int ks = 0; ks < 4; ++ks) {
            ldsm_x4(qh[ks], qa + ks * 32);
            ldsm_x4(ql[ks], qa + FQ_LO + ks * 32);
        }
    }

    float O[8][4];
    #pragma unroll
    for (int n = 0; n < 8; ++n)
        #pragma unroll
        for (int c = 0; c < 4; ++c) O[n][c] = 0.f;
    float m0 = -1e30f, m1 = -1e30f, l0 = 0.f, l1 = 0.f;

    // fragment lane offsets (relative to region start)
    const uint32_t kRel = (uint32_t)((lane & 7) + ((lane >> 4) & 1) * 8) * ASTR
                        + ((lane >> 3) & 1) * 16;
    const uint32_t vRel = (uint32_t)(lane & 15) * ASTR + (uint32_t)(lane >> 4) * 16;

    const int rowbase = qbase + w * 16;
    const int ktMax = qbase / 64 + 1;

    for (int kt = 0; kt <= ktMax; ++kt) {
        const int kvbase = kt * 64;
        CP_WAIT0();          // tile kt landed (this thread's copies)
        __syncthreads();     // cross-thread visibility + everyone done with kt-1
        if (kt + 1 <= ktMax) issueKV(kt + 1);   // other buffer, consumed at kt-1
        CP_COMMIT();

        if (kvbase > rowbase + 15) continue;   // warp tile fully masked

        const uint32_t stK = sb + FKV0 + (uint32_t)(kt & 1) * KVSTG;
        const uint32_t stV = stK + 18432;

        // ---- S = Q K^T -------------------------------------------------------
        float S[8][4];
        #pragma unroll
        for (int n = 0; n < 8; ++n)
            #pragma unroll
            for (int c = 0; c < 4; ++c) S[n][c] = 0.f;

        #pragma unroll
        for (int ks = 0; ks < 4; ++ks) {
            uint32_t kb[4][4], kl_[4][4];
            #pragma unroll
            for (int j = 0; j < 4; ++j) {
                const uint32_t ka = stK + kRel + (uint32_t)j * 16 * ASTR + ks * 32;
                ldsm_x4(kb[j],  ka);
                ldsm_x4(kl_[j], ka + 9216);
            }
            #pragma unroll
            for (int n = 0; n < 8; ++n) {
                const int j = n >> 1, hh = (n & 1) * 2;
                mma16816(S[n], qh[ks], kb[j][hh],  kb[j][hh + 1]);
                mma16816(S[n], qh[ks], kl_[j][hh], kl_[j][hh + 1]);
                mma16816(S[n], ql[ks], kb[j][hh],  kb[j][hh + 1]);
            }
        }

        // scale (exact) + causal mask
        #pragma unroll
        for (int n = 0; n < 8; ++n) {
            S[n][0] *= 0.125f; S[n][1] *= 0.125f;
            S[n][2] *= 0.125f; S[n][3] *= 0.125f;
        }
        if (kvbase + 63 > rowbase) {
            #pragma unroll
            for (int n = 0; n < 8; ++n) {
                const int colb = kvbase + n * 8 + t2;
                if (colb > rowbase + g)          S[n][0] = -1e30f;
                if (colb + 1 > rowbase + g)      S[n][1] = -1e30f;
                if (colb > rowbase + g + 8)      S[n][2] = -1e30f;
                if (colb + 1 > rowbase + g + 8)  S[n][3] = -1e30f;
            }
        }

        // ---- online softmax ---------------------------------------------------
        float tm0 = -1e30f, tm1 = -1e30f;
        #pragma unroll
        for (int n = 0; n < 8; ++n) {
            tm0 = fmaxf(tm0, fmaxf(S[n][0], S[n][1]));
            tm1 = fmaxf(tm1, fmaxf(S[n][2], S[n][3]));
        }
        tm0 = fmaxf(tm0, __shfl_xor_sync(0xFFFFFFFFu, tm0, 1));
        tm0 = fmaxf(tm0, __shfl_xor_sync(0xFFFFFFFFu, tm0, 2));
        tm1 = fmaxf(tm1, __shfl_xor_sync(0xFFFFFFFFu, tm1, 1));
        tm1 = fmaxf(tm1, __shfl_xor_sync(0xFFFFFFFFu, tm1, 2));

        const float mn0 = fmaxf(m0, tm0);
        const float mn1 = fmaxf(m1, tm1);
        const float cr0 = __expf(m0 - mn0);
        const float cr1 = __expf(m1 - mn1);
        l0 *= cr0; l1 *= cr1;
        #pragma unroll
        for (int n = 0; n < 8; ++n) {
            O[n][0] *= cr0; O[n][1] *= cr0;
            O[n][2] *= cr1; O[n][3] *= cr1;
        }
        #pragma unroll
        for (int n = 0; n < 8; ++n) {
            S[n][0] = __expf(S[n][0] - mn0);
            S[n][1] = __expf(S[n][1] - mn0);
            S[n][2] = __expf(S[n][2] - mn1);
            S[n][3] = __expf(S[n][3] - mn1);
            l0 += S[n][0] + S[n][1];
            l1 += S[n][2] + S[n][3];
        }
        m0 = mn0; m1 = mn1;

        // ---- pack P fragments (hi/lo) -----------------------------------------
        uint32_t ph[4][4], pl[4][4];
        #pragma unroll
        for (int j = 0; j < 4; ++j) {
            split2(S[2 * j][0],     S[2 * j][1],     ph[j][0], pl[j][0]);
            split2(S[2 * j][2],     S[2 * j][3],     ph[j][1], pl[j][1]);
            split2(S[2 * j + 1][0], S[2 * j + 1][1], ph[j][2], pl[j][2]);
            split2(S[2 * j + 1][2], S[2 * j + 1][3], ph[j][3], pl[j][3]);
        }

        // ---- O += P V -----------------------------------------------------------
        #pragma unroll
        for (int ks = 0; ks < 4; ++ks) {
            uint32_t vb[4][4], vl_[4][4];
            #pragma unroll
            for (int j = 0; j < 4; ++j) {
                const uint32_t va = stV + vRel + (uint32_t)ks * 16 * ASTR + (uint32_t)j * 32;
                ldsm_x4_t(vb[j],  va);
                ldsm_x4_t(vl_[j], va + 9216);
            }
            #pragma unroll
            for (int n = 0; n < 8; ++n) {
                const int j = n >> 1, hh = (n & 1) * 2;
                mma16816(O[n], ph[ks], vb[j][hh],  vb[j][hh + 1]);
                mma16816(O[n], ph[ks], vl_[j][hh], vl_[j][hh + 1]);
                mma16816(O[n], pl[ks], vb[j][hh],  vb[j][hh + 1]);
            }
        }
    }
    CP_WAIT0();

    // ---- finalize: reduce l, scale, split-store ------------------------------
    l0 += __shfl_xor_sync(0xFFFFFFFFu, l0, 1);
    l0 += __shfl_xor_sync(0xFFFFFFFFu, l0, 2);
    l1 += __shfl_xor_sync(0xFFFFFFFFu, l1, 1);
    l1 += __shfl_xor_sync(0xFFFFFFFFu, l1, 2);
    const float inv0 = 1.f / l0;
    const float inv1 = 1.f / l1;

    const size_t row0 = (size_t)(b * SS + rowbase + g);
    #pragma unroll
    for (int n = 0; n < 8; ++n) {
        const int c = h * DEPTH + n * 8 + t2;
        uint32_t hi, lo;
        split2(O[n][0] * inv0, O[n][1] * inv0, hi, lo);
        *(uint32_t*)&outh[row0 * DD + c] = hi;
        *(uint32_t*)&outl[row0 * DD + c] = lo;
        split2(O[n][2] * inv1, O[n][3] * inv1, hi, lo);
        *(uint32_t*)&outh[(row0 + 8) * DD + c] = hi;
        *(uint32_t*)&outl[(row0 + 8) * DD + c] = lo;
    }
}

// ---------------------------------------------------------------------------
// Launch: 3 split preps -> QKV GEMM(split out) -> flash attn -> out GEMM(f32).
// ---------------------------------------------------------------------------
extern "C" void kernel_launch(void* const* d_in, const int* in_sizes, int n_in,
                              void* d_out, int out_size)
{
    const float* x     = (const float*)d_in[0];
    const float* Wqkv  = (const float*)d_in[2];
    const float* bqkv  = (const float*)d_in[3];
    const float* Wout  = (const float*)d_in[4];
    const float* bout  = (const float*)d_in[5];
    float* out = (float*)d_out;

    __nv_bfloat16 *xh, *xl, *wqh, *wql, *woh, *wol, *qh, *ql, *ah, *al;
    { void* p; cudaGetSymbolAddress(&p, g_xh);  xh  = (__nv_bfloat16*)p; }
    { void* p; cudaGetSymbolAddress(&p, g_xl);  xl  = (__nv_bfloat16*)p; }
    { void* p; cudaGetSymbolAddress(&p, g_wqh); wqh = (__nv_bfloat16*)p; }
    { void* p; cudaGetSymbolAddress(&p, g_wql); wql = (__nv_bfloat16*)p; }
    { void* p; cudaGetSymbolAddress(&p, g_woh); woh = (__nv_bfloat16*)p; }
    { void* p; cudaGetSymbolAddress(&p, g_wol); wol = (__nv_bfloat16*)p; }
    { void* p; cudaGetSymbolAddress(&p, g_qh);  qh  = (__nv_bfloat16*)p; }
    { void* p; cudaGetSymbolAddress(&p, g_ql);  ql  = (__nv_bfloat16*)p; }
    { void* p; cudaGetSymbolAddress(&p, g_ah);  ah  = (__nv_bfloat16*)p; }
    { void* p; cudaGetSymbolAddress(&p, g_al);  al  = (__nv_bfloat16*)p; }

    static bool attr_set = false;
    if (!attr_set) {
        cudaFuncSetAttribute(tgemm_bf16_kernel<true>,
                             cudaFuncAttributeMaxDynamicSharedMemorySize, G_SMEM);
        cudaFuncSetAttribute(tgemm_bf16_kernel<false>,
                             cudaFuncAttributeMaxDynamicSharedMemorySize, G_SMEM);
        cudaFuncSetAttribute(fattn_kernel,
                             cudaFuncAttributeMaxDynamicSharedMemorySize, FATTN_SMEM);
        attr_set = true;
    }

    // 0) pre-split inputs/weights to bf16 hi/lo
    split_kernel<<<(MROWS * DD / 4 + 255) / 256, 256>>>(x, xh, xl, MROWS * DD);
    split_kernel<<<(DD * QKV_N / 4 + 255) / 256, 256>>>(Wqkv, wqh, wql, DD * QKV_N);
    split_kernel<<<(DD * DD / 4 + 255) / 256, 256>>>(Wout, woh, wol, DD * DD);

    // 1) QKV projection -> split bf16 qkv
    {
        dim3 grid(QKV_N / 128, MROWS / 128);
        tgemm_bf16_kernel<true><<<grid, 256, G_SMEM>>>(
            xh, xl, wqh, wql, bqkv, qh, ql, QKV_N, DD);
    }
    // 2) causal flash attention -> split bf16 attn
    {
        dim3 grid(SS / 128, BB * HH);
        fattn_kernel<<<grid, 256, FATTN_SMEM>>>(qh, ql, ah, al);
    }
    // 3) output projection -> fp32 out
    {
        dim3 grid(DD / 128, MROWS / 128);
        tgemm_bf16_kernel<false><<<grid, 256, G_SMEM>>>(
            ah, al, woh, wol, bout, out, nullptr, DD, DD);
    }
}

// round 8
// speedup vs baseline: 3.2474x; 1.0138x over previous
#include <cuda_runtime.h>
#include <cuda_bf16.h>
#include <cstdint>

// Problem constants
#define BB 2
#define SS 2048
#define DD 1024
#define HH 16
#define DEPTH 64
#define MROWS (BB * SS)          // 4096
#define QKV_N (3 * DD)           // 3072

// Scratch (allocation-free rule: __device__ globals), all bf16 hi/lo pairs
__device__ __nv_bfloat16 g_xh[MROWS * DD],    g_xl[MROWS * DD];
__device__ __nv_bfloat16 g_wqh[DD * QKV_N],   g_wql[DD * QKV_N];
__device__ __nv_bfloat16 g_woh[DD * DD],      g_wol[DD * DD];
__device__ __nv_bfloat16 g_qh[MROWS * QKV_N], g_ql[MROWS * QKV_N];
__device__ __nv_bfloat16 g_ah[MROWS * DD],    g_al[MROWS * DD];

// ===========================================================================
// Helpers (base-target PTX: sm_80+, works on sm_103)
// ===========================================================================
__device__ __forceinline__ uint32_t smem_u32(const void* p) {
    uint32_t a;
    asm("{ .reg .u64 t; cvta.to.shared.u64 t, %1; cvt.u32.u64 %0, t; }"
        : "=r"(a) : "l"(p));
    return a;
}

__device__ __forceinline__ void ldsm_x4(uint32_t* r, uint32_t a) {
    asm volatile("ldmatrix.sync.aligned.m8n8.x4.shared.b16 {%0,%1,%2,%3}, [%4];"
                 : "=r"(r[0]), "=r"(r[1]), "=r"(r[2]), "=r"(r[3]) : "r"(a));
}

__device__ __forceinline__ void ldsm_x4_t(uint32_t* r, uint32_t a) {
    asm volatile("ldmatrix.sync.aligned.m8n8.x4.trans.shared.b16 {%0,%1,%2,%3}, [%4];"
                 : "=r"(r[0]), "=r"(r[1]), "=r"(r[2]), "=r"(r[3]) : "r"(a));
}

__device__ __forceinline__ void mma16816(float* c, const uint32_t* a,
                                         uint32_t b0, uint32_t b1) {
    asm volatile(
        "mma.sync.aligned.m16n8k16.row.col.f32.bf16.bf16.f32 "
        "{%0,%1,%2,%3}, {%4,%5,%6,%7}, {%8,%9}, {%0,%1,%2,%3};"
        : "+f"(c[0]), "+f"(c[1]), "+f"(c[2]), "+f"(c[3])
        : "r"(a[0]), "r"(a[1]), "r"(a[2]), "r"(a[3]), "r"(b0), "r"(b1));
}

__device__ __forceinline__ void cpa16(uint32_t d, const void* s) {
    asm volatile("cp.async.cg.shared.global [%0], [%1], 16;" :: "r"(d), "l"(s));
}
#define CP_COMMIT() asm volatile("cp.async.commit_group;" ::: "memory")
#define CP_WAIT1()  asm volatile("cp.async.wait_group 1;" ::: "memory")
#define CP_WAIT0()  asm volatile("cp.async.wait_group 0;" ::: "memory")

// Split fp32 -> (hi: truncated bf16, lo: rn bf16 of residual). Packs 2 at once.
__device__ __forceinline__ void split2(float x0, float x1,
                                       uint32_t& hi, uint32_t& lo) {
    uint32_t u0 = __float_as_uint(x0), u1 = __float_as_uint(x1);
    uint32_t h0 = u0 & 0xFFFF0000u,    h1 = u1 & 0xFFFF0000u;
    float l0 = x0 - __uint_as_float(h0);
    float l1 = x1 - __uint_as_float(h1);
    hi = (h0 >> 16) | h1;
    __nv_bfloat162 lp = __float22bfloat162_rn(make_float2(l0, l1));
    lo = *reinterpret_cast<uint32_t*>(&lp);
}

// ===========================================================================
// Prep: elementwise fp32 -> bf16 hi/lo split
// ===========================================================================
__global__ void split_kernel(const float* __restrict__ in,
                             __nv_bfloat16* __restrict__ oh,
                             __nv_bfloat16* __restrict__ ol, int n)
{
    const int i = (blockIdx.x * blockDim.x + threadIdx.x) * 4;
    if (i >= n) return;
    float4 v = *(const float4*)(in + i);
    uint32_t h0, l0, h1, l1;
    split2(v.x, v.y, h0, l0);
    split2(v.z, v.w, h1, l1);
    *(uint2*)(oh + i) = make_uint2(h0, h1);
    *(uint2*)(ol + i) = make_uint2(l0, l1);
}

// ===========================================================================
// bf16 hi/lo GEMM + bias, cp.async 3-stage, one sync per chunk.
// BM=64, BN=128, BK=32. 8 warps = 2(m) x 4(n), warp tile 32x32.
// Per warp-chunk: 48 MMA vs 16 LDSM (ratio 3).
// Stage (27648 B): Ah 0 (64x80) | Al 5120 | Bh 10240 (32x272) | Bl 18944
// ===========================================================================
#define GSTAGE 27648
#define G_SMEM (3 * GSTAGE)

template<bool SPLIT_OUT>
__global__ __launch_bounds__(256, 2) void tgemm_bf16_kernel(
    const __nv_bfloat16* __restrict__ Ah, const __nv_bfloat16* __restrict__ Al,
    const __nv_bfloat16* __restrict__ Bh, const __nv_bfloat16* __restrict__ Bl,
    const float* __restrict__ bias,
    void* __restrict__ Cp, void* __restrict__ Clp,
    int N, int K)
{
    extern __shared__ char sm[];
    const uint32_t sb = smem_u32(sm);

    const int tid  = threadIdx.x;
    const int lane = tid & 31;
    const int wid  = tid >> 5;
    const int wm   = wid & 1;          // 0..1 -> rows wm*32
    const int wn   = wid >> 1;         // 0..3 -> cols wn*32

    const int rowBase = blockIdx.y * 64;
    const int colBase = blockIdx.x * 128;

    // loader mappings
    const int aRow = tid >> 2;             // 0..63
    const int aE0  = (tid & 3) * 8;        // 0,8,16,24 elems
    const int bK   = tid >> 3;             // 0..31
    const int bE0  = (tid & 7) * 16;       // 0..112 elems

    // ldmatrix bases (relative to stage start)
    const int laneM = lane & 15;
    const int laneH = lane >> 4;
    uint32_t aRel[2], bRel[2];
    #pragma unroll
    for (int i = 0; i < 2; ++i)
        aRel[i] = (uint32_t)(wm * 32 + i * 16 + laneM) * 80 + laneH * 16;
    #pragma unroll
    for (int j = 0; j < 2; ++j)
        bRel[j] = 10240u + (uint32_t)laneM * 272
                + (uint32_t)(wn * 32 + j * 16 + laneH * 8) * 2;

    float acc[2][4][4];
    #pragma unroll
    for (int i = 0; i < 2; ++i)
        #pragma unroll
        for (int n = 0; n < 4; ++n)
            #pragma unroll
            for (int c = 0; c < 4; ++c) acc[i][n][c] = 0.f;

    const int nChunks = K >> 5;

    auto issue = [&](int ck, uint32_t stOff) {
        const uint32_t st = sb + stOff;
        const int k0 = ck << 5;
        {   // A rows: 4 threads/row, 8 elems (16B) each
            const size_t gi = (size_t)(rowBase + aRow) * K + k0 + aE0;
            const uint32_t d = st + (uint32_t)aRow * 80 + aE0 * 2;
            cpa16(d,        Ah + gi);
            cpa16(d + 5120, Al + gi);
        }
        {   // B rows [k][n]: 8 threads/row, 16 elems (2x16B) each
            const size_t gi = (size_t)(k0 + bK) * N + colBase + bE0;
            const uint32_t d = st + 10240u + (uint32_t)bK * 272 + bE0 * 2;
            cpa16(d,             Bh + gi);
            cpa16(d + 16,        Bh + gi + 8);
            cpa16(d + 8704,      Bl + gi);
            cpa16(d + 8704 + 16, Bl + gi + 8);
        }
    };

    issue(0, 0); CP_COMMIT();
    issue(1, GSTAGE); CP_COMMIT();

    uint32_t stOff = 0;
    for (int ck = 0; ck < nChunks; ++ck) {
        CP_WAIT1();          // chunk ck complete (ck+1 may be in flight)
        __syncthreads();     // visibility + everyone done with chunk ck-1
        if (ck + 2 < nChunks) {
            uint32_t issOff = stOff + 2 * GSTAGE;
            if (issOff >= 3 * GSTAGE) issOff -= 3 * GSTAGE;
            issue(ck + 2, issOff);
        }
        CP_COMMIT();

        const uint32_t st = sb + stOff;
        #pragma unroll
        for (int ks = 0; ks < 2; ++ks) {
            const uint32_t aOff = st + ks * 32;
            const uint32_t bOff = st + ks * 16 * 272;
            uint32_t ah[2][4], al[2][4], bh[2][4], bl[2][4];
            #pragma unroll
            for (int i = 0; i < 2; ++i) {
                ldsm_x4(ah[i], aRel[i] + aOff);
                ldsm_x4(al[i], aRel[i] + aOff + 5120);
            }
            #pragma unroll
            for (int j = 0; j < 2; ++j) {
                ldsm_x4_t(bh[j], bRel[j] + bOff);
                ldsm_x4_t(bl[j], bRel[j] + bOff + 8704);
            }
            #pragma unroll
            for (int i = 0; i < 2; ++i) {
                #pragma unroll
                for (int n = 0; n < 4; ++n) {
                    const int j = n >> 1, h = (n & 1) * 2;
                    mma16816(acc[i][n], ah[i], bh[j][h], bh[j][h + 1]);
                    mma16816(acc[i][n], ah[i], bl[j][h], bl[j][h + 1]);
                    mma16816(acc[i][n], al[i], bh[j][h], bh[j][h + 1]);
                }
            }
        }
        stOff += GSTAGE;
        if (stOff >= 3 * GSTAGE) stOff = 0;
    }
    CP_WAIT0();

    // ---- epilogue ----------------------------------------------------------
    #pragma unroll
    for (int i = 0; i < 2; ++i) {
        const int r0 = rowBase + wm * 32 + i * 16 + (lane >> 2);
        #pragma unroll
        for (int n = 0; n < 4; ++n) {
            const int c = colBase + wn * 32 + n * 8 + (lane & 3) * 2;
            const float b0 = bias[c], b1 = bias[c + 1];
            const float v00 = acc[i][n][0] + b0, v01 = acc[i][n][1] + b1;
            const float v10 = acc[i][n][2] + b0, v11 = acc[i][n][3] + b1;
            if (SPLIT_OUT) {
                __nv_bfloat16* Ch = (__nv_bfloat16*)Cp;
                __nv_bfloat16* Cl = (__nv_bfloat16*)Clp;
                uint32_t hi, lo;
                split2(v00, v01, hi, lo);
                *(uint32_t*)&Ch[(size_t)r0 * N + c] = hi;
                *(uint32_t*)&Cl[(size_t)r0 * N + c] = lo;
                split2(v10, v11, hi, lo);
                *(uint32_t*)&Ch[(size_t)(r0 + 8) * N + c] = hi;
                *(uint32_t*)&Cl[(size_t)(r0 + 8) * N + c] = lo;
            } else {
                float* C = (float*)Cp;
                *(float2*)&C[(size_t)r0 * N + c]       = make_float2(v00, v01);
                *(float2*)&C[(size_t)(r0 + 8) * N + c] = make_float2(v10, v11);
            }
        }
    }
}

// ===========================================================================
// Tensor-core causal flash attention, bf16 hi/lo I/O (unchanged from R7).
// CTA = 128 q rows x one (b,h); 8 warps x 16 rows; kv tiles of 64.
// K/V staged via cp.async, double-buffered: ONE sync per kv tile.
// smem: Q_hi 0, Q_lo 18432; KV stage s at 36864 + s*36864:
//       K_hi +0, K_lo +9216, V_hi +18432, V_lo +27648. Total 110592.
// ===========================================================================
#define ASTR 144
#define FQ_LO 18432
#define FKV0 36864
#define KVSTG 36864
#define FATTN_SMEM 110592

__global__ __launch_bounds__(256, 2) void fattn_kernel(
    const __nv_bfloat16* __restrict__ qkvh,
    const __nv_bfloat16* __restrict__ qkvl,
    __nv_bfloat16* __restrict__ outh,
    __nv_bfloat16* __restrict__ outl)
{
    extern __shared__ char sm[];
    const uint32_t sb = smem_u32(sm);

    const int tid  = threadIdx.x;
    const int lane = tid & 31;
    const int w    = tid >> 5;
    const int g    = lane >> 2;
    const int t2   = (lane & 3) * 2;

    const int qt = (gridDim.x - 1) - blockIdx.x;   // heavy tiles first
    const int bh = blockIdx.y;
    const int b  = bh >> 4;
    const int h  = bh & 15;
    const int qbase = qt * 128;

    const int kvR  = tid >> 2;
    const int kvC0 = (tid & 3) * 16;
    auto issueKV = [&](int kt) {
        const uint32_t st = sb + FKV0 + (uint32_t)(kt & 1) * KVSTG;
        const size_t gi = (size_t)(b * SS + kt * 64 + kvR) * QKV_N + h * 192 + 64 + kvC0;
        const uint32_t d = st + (uint32_t)kvR * ASTR + kvC0 * 2;
        cpa16(d,              qkvh + gi);          // K hi
        cpa16(d + 16,         qkvh + gi + 8);
        cpa16(d + 9216,       qkvl + gi);          // K lo
        cpa16(d + 9216 + 16,  qkvl + gi + 8);
        cpa16(d + 18432,      qkvh + gi + 64);     // V hi
        cpa16(d + 18432 + 16, qkvh + gi + 72);
        cpa16(d + 27648,      qkvl + gi + 64);     // V lo
        cpa16(d + 27648 + 16, qkvl + gi + 72);
    };

    // ---- stage Q (plain stores) + kick off kv tile 0 -------------------------
    {
        const int qrow = tid >> 1;
        const int qc0  = (tid & 1) * 32;
        const size_t gi = (size_t)(b * SS + qbase + qrow) * QKV_N + h * 192 + qc0;
        char* dh = sm + qrow * ASTR + qc0 * 2;
        char* dl = sm + FQ_LO + qrow * ASTR + qc0 * 2;
        #pragma unroll
        for (int j = 0; j < 4; ++j) {
            *(uint4*)(dh + j * 16) = *(const uint4*)(qkvh + gi + j * 8);
            *(uint4*)(dl + j * 16) = *(const uint4*)(qkvl + gi + j * 8);
        }
    }
    issueKV(0); CP_COMMIT();
    __syncthreads();

    // ---- Q fragments in registers for whole kv loop --------------------------
    uint32_t qh[4][4], ql[4][4];
    {
        const uint32_t qa = sb + (uint32_t)(w * 16 + (lane & 15)) * ASTR + (lane >> 4) * 16;
        #pragma unroll
        for (int ks = 0; ks < 4; ++ks) {
            ldsm_x4(qh[ks], qa + ks * 32);
            ldsm_x4(ql[ks], qa + FQ_LO + ks * 32);
        }
    }

    float O[8][4];
    #pragma unroll
    for (int n = 0; n < 8; ++n)
        #pragma unroll
        for (int c = 0; c < 4; ++c) O[n][c] = 0.f;
    float m0 = -1e30f, m1 = -1e30f, l0 = 0.f, l1 = 0.f;

    const uint32_t kRel = (uint32_t)((lane & 7) + ((lane >> 4) & 1) * 8) * ASTR
                        + ((lane >> 3) & 1) * 16;
    const uint32_t vRel = (uint32_t)(lane & 15) * ASTR + (uint32_t)(lane >> 4) * 16;

    const int rowbase = qbase + w * 16;
    const int ktMax = qbase / 64 + 1;

    for (int kt = 0; kt <= ktMax; ++kt) {
        const int kvbase = kt * 64;
        CP_WAIT0();
        __syncthreads();
        if (kt + 1 <= ktMax) issueKV(kt + 1);
        CP_COMMIT();

        if (kvbase > rowbase + 15) continue;

        const uint32_t stK = sb + FKV0 + (uint32_t)(kt & 1) * KVSTG;
        const uint32_t stV = stK + 18432;

        // ---- S = Q K^T -------------------------------------------------------
        float S[8][4];
        #pragma unroll
        for (int n = 0; n < 8; ++n)
            #pragma unroll
            for (int c = 0; c < 4; ++c) S[n][c] = 0.f;

        #pragma unroll
        for (int ks = 0; ks < 4; ++ks) {
            uint32_t kb[4][4], kl_[4][4];
            #pragma unroll
            for (int j = 0; j < 4; ++j) {
                const uint32_t ka = stK + kRel + (uint32_t)j * 16 * ASTR + ks * 32;
                ldsm_x4(kb[j],  ka);
                ldsm_x4(kl_[j], ka + 9216);
            }
            #pragma unroll
            for (int n = 0; n < 8; ++n) {
                const int j = n >> 1, hh = (n & 1) * 2;
                mma16816(S[n], qh[ks], kb[j][hh],  kb[j][hh + 1]);
                mma16816(S[n], qh[ks], kl_[j][hh], kl_[j][hh + 1]);
                mma16816(S[n], ql[ks], kb[j][hh],  kb[j][hh + 1]);
            }
        }

        // scale (exact) + causal mask
        #pragma unroll
        for (int n = 0; n < 8; ++n) {
            S[n][0] *= 0.125f; S[n][1] *= 0.125f;
            S[n][2] *= 0.125f; S[n][3] *= 0.125f;
        }
        if (kvbase + 63 > rowbase) {
            #pragma unroll
            for (int n = 0; n < 8; ++n) {
                const int colb = kvbase + n * 8 + t2;
                if (colb > rowbase + g)          S[n][0] = -1e30f;
                if (colb + 1 > rowbase + g)      S[n][1] = -1e30f;
                if (colb > rowbase + g + 8)      S[n][2] = -1e30f;
                if (colb + 1 > rowbase + g + 8)  S[n][3] = -1e30f;
            }
        }

        // ---- online softmax ---------------------------------------------------
        float tm0 = -1e30f, tm1 = -1e30f;
        #pragma unroll
        for (int n = 0; n < 8; ++n) {
            tm0 = fmaxf(tm0, fmaxf(S[n][0], S[n][1]));
            tm1 = fmaxf(tm1, fmaxf(S[n][2], S[n][3]));
        }
        tm0 = fmaxf(tm0, __shfl_xor_sync(0xFFFFFFFFu, tm0, 1));
        tm0 = fmaxf(tm0, __shfl_xor_sync(0xFFFFFFFFu, tm0, 2));
        tm1 = fmaxf(tm1, __shfl_xor_sync(0xFFFFFFFFu, tm1, 1));
        tm1 = fmaxf(tm1, __shfl_xor_sync(0xFFFFFFFFu, tm1, 2));

        const float mn0 = fmaxf(m0, tm0);
        const float mn1 = fmaxf(m1, tm1);
        const float cr0 = __expf(m0 - mn0);
        const float cr1 = __expf(m1 - mn1);
        l0 *= cr0; l1 *= cr1;
        #pragma unroll
        for (int n = 0; n < 8; ++n) {
            O[n][0] *= cr0; O[n][1] *= cr0;
            O[n][2] *= cr1; O[n][3] *= cr1;
        }
        #pragma unroll
        for (int n = 0; n < 8; ++n) {
            S[n][0] = __expf(S[n][0] - mn0);
            S[n][1] = __expf(S[n][1] - mn0);
            S[n][2] = __expf(S[n][2] - mn1);
            S[n][3] = __expf(S[n][3] - mn1);
            l0 += S[n][0] + S[n][1];
            l1 += S[n][2] + S[n][3];
        }
        m0 = mn0; m1 = mn1;

        // ---- pack P fragments (hi/lo) -----------------------------------------
        uint32_t ph[4][4], pl[4][4];
        #pragma unroll
        for (int j = 0; j < 4; ++j) {
            split2(S[2 * j][0],     S[2 * j][1],     ph[j][0], pl[j][0]);
            split2(S[2 * j][2],     S[2 * j][3],     ph[j][1], pl[j][1]);
            split2(S[2 * j + 1][0], S[2 * j + 1][1], ph[j][2], pl[j][2]);
            split2(S[2 * j + 1][2], S[2 * j + 1][3], ph[j][3], pl[j][3]);
        }

        // ---- O += P V -----------------------------------------------------------
        #pragma unroll
        for (int ks = 0; ks < 4; ++ks) {
            uint32_t vb[4][4], vl_[4][4];
            #pragma unroll
            for (int j = 0; j < 4; ++j) {
                const uint32_t va = stV + vRel + (uint32_t)ks * 16 * ASTR + (uint32_t)j * 32;
                ldsm_x4_t(vb[j],  va);
                ldsm_x4_t(vl_[j], va + 9216);
            }
            #pragma unroll
            for (int n = 0; n < 8; ++n) {
                const int j = n >> 1, hh = (n & 1) * 2;
                mma16816(O[n], ph[ks], vb[j][hh],  vb[j][hh + 1]);
                mma16816(O[n], ph[ks], vl_[j][hh], vl_[j][hh + 1]);
                mma16816(O[n], pl[ks], vb[j][hh],  vb[j][hh + 1]);
            }
        }
    }
    CP_WAIT0();

    // ---- finalize: reduce l, scale, split-store ------------------------------
    l0 += __shfl_xor_sync(0xFFFFFFFFu, l0, 1);
    l0 += __shfl_xor_sync(0xFFFFFFFFu, l0, 2);
    l1 += __shfl_xor_sync(0xFFFFFFFFu, l1, 1);
    l1 += __shfl_xor_sync(0xFFFFFFFFu, l1, 2);
    const float inv0 = 1.f / l0;
    const float inv1 = 1.f / l1;

    const size_t row0 = (size_t)(b * SS + rowbase + g);
    #pragma unroll
    for (int n = 0; n < 8; ++n) {
        const int c = h * DEPTH + n * 8 + t2;
        uint32_t hi, lo;
        split2(O[n][0] * inv0, O[n][1] * inv0, hi, lo);
        *(uint32_t*)&outh[row0 * DD + c] = hi;
        *(uint32_t*)&outl[row0 * DD + c] = lo;
        split2(O[n][2] * inv1, O[n][3] * inv1, hi, lo);
        *(uint32_t*)&outh[(row0 + 8) * DD + c] = hi;
        *(uint32_t*)&outl[(row0 + 8) * DD + c] = lo;
    }
}

// ---------------------------------------------------------------------------
// Launch: 3 split preps -> QKV GEMM(split out) -> flash attn -> out GEMM(f32).
// ---------------------------------------------------------------------------
extern "C" void kernel_launch(void* const* d_in, const int* in_sizes, int n_in,
                              void* d_out, int out_size)
{
    const float* x     = (const float*)d_in[0];
    const float* Wqkv  = (const float*)d_in[2];
    const float* bqkv  = (const float*)d_in[3];
    const float* Wout  = (const float*)d_in[4];
    const float* bout  = (const float*)d_in[5];
    float* out = (float*)d_out;

    __nv_bfloat16 *xh, *xl, *wqh, *wql, *woh, *wol, *qh, *ql, *ah, *al;
    { void* p; cudaGetSymbolAddress(&p, g_xh);  xh  = (__nv_bfloat16*)p; }
    { void* p; cudaGetSymbolAddress(&p, g_xl);  xl  = (__nv_bfloat16*)p; }
    { void* p; cudaGetSymbolAddress(&p, g_wqh); wqh = (__nv_bfloat16*)p; }
    { void* p; cudaGetSymbolAddress(&p, g_wql); wql = (__nv_bfloat16*)p; }
    { void* p; cudaGetSymbolAddress(&p, g_woh); woh = (__nv_bfloat16*)p; }
    { void* p; cudaGetSymbolAddress(&p, g_wol); wol = (__nv_bfloat16*)p; }
    { void* p; cudaGetSymbolAddress(&p, g_qh);  qh  = (__nv_bfloat16*)p; }
    { void* p; cudaGetSymbolAddress(&p, g_ql);  ql  = (__nv_bfloat16*)p; }
    { void* p; cudaGetSymbolAddress(&p, g_ah);  ah  = (__nv_bfloat16*)p; }
    { void* p; cudaGetSymbolAddress(&p, g_al);  al  = (__nv_bfloat16*)p; }

    static bool attr_set = false;
    if (!attr_set) {
        cudaFuncSetAttribute(tgemm_bf16_kernel<true>,
                             cudaFuncAttributeMaxDynamicSharedMemorySize, G_SMEM);
        cudaFuncSetAttribute(tgemm_bf16_kernel<false>,
                             cudaFuncAttributeMaxDynamicSharedMemorySize, G_SMEM);
        cudaFuncSetAttribute(fattn_kernel,
                             cudaFuncAttributeMaxDynamicSharedMemorySize, FATTN_SMEM);
        attr_set = true;
    }

    // 0) pre-split inputs/weights to bf16 hi/lo
    split_kernel<<<(MROWS * DD / 4 + 255) / 256, 256>>>(x, xh, xl, MROWS * DD);
    split_kernel<<<(DD * QKV_N / 4 + 255) / 256, 256>>>(Wqkv, wqh, wql, DD * QKV_N);
    split_kernel<<<(DD * DD / 4 + 255) / 256, 256>>>(Wout, woh, wol, DD * DD);

    // 1) QKV projection -> split bf16 qkv
    {
        dim3 grid(QKV_N / 128, MROWS / 64);
        tgemm_bf16_kernel<true><<<grid, 256, G_SMEM>>>(
            xh, xl, wqh, wql, bqkv, qh, ql, QKV_N, DD);
    }
    // 2) causal flash attention -> split bf16 attn
    {
        dim3 grid(SS / 128, BB * HH);
        fattn_kernel<<<grid, 256, FATTN_SMEM>>>(qh, ql, ah, al);
    }
    // 3) output projection -> fp32 out
    {
        dim3 grid(DD / 128, MROWS / 64);
        tgemm_bf16_kernel<false><<<grid, 256, G_SMEM>>>(
            ah, al, woh, wol, bout, out, nullptr, DD, DD);
    }
}